// round 9
// baseline (speedup 1.0000x reference)
#include <cuda_runtime.h>
#include <cuda_fp16.h>
#include <cstdint>

#define NSEQ 4096
#define CDIM 256
#define HEADS 8
#define DDIM 64
#define HD   512
#define LDQ  72   // fp16 smem leading dim (144B stride -> conflict-free ldmatrix)
#define NT   (NSEQ / 64)

// Scratch (static device arrays; no allocation allowed)
__device__ __half g_qh[NSEQ * HD];
__device__ __half g_kh[NSEQ * HD];
__device__ __half g_vh[NSEQ * HD];
__device__ float  g_g [NSEQ * HD];
__device__ __half g_oh[NSEQ * HD];

// ---------------------------------------------------------------------------
// PTX helpers
// ---------------------------------------------------------------------------
__device__ __forceinline__ uint32_t smaddr(const void* p) {
    return (uint32_t)__cvta_generic_to_shared(p);
}

__device__ __forceinline__ void ldsm_x4(uint32_t& r0, uint32_t& r1, uint32_t& r2, uint32_t& r3,
                                        uint32_t addr) {
    asm volatile("ldmatrix.sync.aligned.m8n8.x4.shared.b16 {%0,%1,%2,%3}, [%4];"
                 : "=r"(r0), "=r"(r1), "=r"(r2), "=r"(r3) : "r"(addr));
}

__device__ __forceinline__ void ldsm_x4_t(uint32_t& r0, uint32_t& r1, uint32_t& r2, uint32_t& r3,
                                          uint32_t addr) {
    asm volatile("ldmatrix.sync.aligned.m8n8.x4.trans.shared.b16 {%0,%1,%2,%3}, [%4];"
                 : "=r"(r0), "=r"(r1), "=r"(r2), "=r"(r3) : "r"(addr));
}

// f32-accumulate variant (projection GEMMs)
__device__ __forceinline__ void mma16816(float* d, const uint32_t* a, uint32_t b0, uint32_t b1) {
    asm volatile(
        "mma.sync.aligned.m16n8k16.row.col.f32.f16.f16.f32 "
        "{%0,%1,%2,%3}, {%4,%5,%6,%7}, {%8,%9}, {%0,%1,%2,%3};"
        : "+f"(d[0]), "+f"(d[1]), "+f"(d[2]), "+f"(d[3])
        : "r"(a[0]), "r"(a[1]), "r"(a[2]), "r"(a[3]), "r"(b0), "r"(b1));
}

// f16-accumulate variant (QK^T and per-tile PV)
__device__ __forceinline__ void mma16816_h(uint32_t* d, const uint32_t* a, uint32_t b0, uint32_t b1) {
    asm volatile(
        "mma.sync.aligned.m16n8k16.row.col.f16.f16.f16.f16 "
        "{%0,%1}, {%2,%3,%4,%5}, {%6,%7}, {%0,%1};"
        : "+r"(d[0]), "+r"(d[1])
        : "r"(a[0]), "r"(a[1]), "r"(a[2]), "r"(a[3]), "r"(b0), "r"(b1));
}

// Pack two fp32 into f16x2: result = {lo=x, hi=y}
__device__ __forceinline__ uint32_t pack_f16x2(float x, float y) {
    uint32_t r;
    asm("{\n\t.reg .b16 lo, hi;\n\t"
        "cvt.rn.f16.f32 lo, %1;\n\t"
        "cvt.rn.f16.f32 hi, %2;\n\t"
        "mov.b32 %0, {lo, hi};\n\t}"
        : "=r"(r) : "f"(x), "f"(y));
    return r;
}

__device__ __forceinline__ void cp_async16(uint32_t dst, const void* src) {
    asm volatile("cp.async.cg.shared.global [%0], [%1], 16;" :: "r"(dst), "l"(src));
}
__device__ __forceinline__ void cp_commit() {
    asm volatile("cp.async.commit_group;");
}
template <int N>
__device__ __forceinline__ void cp_wait() {
    asm volatile("cp.async.wait_group %0;" :: "n"(N));
}

// ---------------------------------------------------------------------------
// Merged projection GEMMs: one launch, blockIdx.z in {0:q, 1:k, 2:v, 3:gate}
// C[m, n] = sum_c X[m, c] * W[n, c], tile M=128 x N=64, K-chunks of 64.
// Software-pipelined: LDGs for chunk k+1 in flight during mma of chunk k.
// ---------------------------------------------------------------------------
__global__ void __launch_bounds__(256) proj_all(const float* __restrict__ q_x,
                                                const float* __restrict__ k_x,
                                                const float* __restrict__ v_x,
                                                const float* __restrict__ wq,
                                                const float* __restrict__ wk,
                                                const float* __restrict__ wv,
                                                const float* __restrict__ wg,
                                                const float* __restrict__ bg) {
    __shared__ __half As[128 * LDQ];
    __shared__ __half Bs[64 * LDQ];

    const int z = blockIdx.z;
    const float* A = (z == 1) ? k_x : (z == 2) ? v_x : q_x;
    const float* B = (z == 0) ? wq : (z == 1) ? wk : (z == 2) ? wv : wg;

    const int m0 = blockIdx.y * 128, n0 = blockIdx.x * 64;
    const int tid = threadIdx.x;
    const int warp = tid >> 5;
    const int lane = tid & 31;
    const int g = lane >> 2, t = lane & 3;

    const int a_row = 16 * warp + (lane & 15);
    const int a_ch  = (lane >> 4) * 8;
    const int b_row = ((lane >> 4) & 1) * 8 + (lane & 7);
    const int b_ch  = ((lane >> 3) & 1) * 8;

    const int srow = tid >> 4;
    const int sc4  = (tid & 15) * 4;

    float acc[8][4] = {};
    float4 ar[8], br[4];

#pragma unroll
    for (int i = 0; i < 8; i++)
        ar[i] = *(const float4*)(A + (size_t)(m0 + srow + 16 * i) * CDIM + sc4);
#pragma unroll
    for (int i = 0; i < 4; i++)
        br[i] = *(const float4*)(B + (size_t)(n0 + srow + 16 * i) * CDIM + sc4);

    for (int k0 = 0; k0 < CDIM; k0 += 64) {
#pragma unroll
        for (int i = 0; i < 8; i++) {
            uint2 p;
            p.x = pack_f16x2(ar[i].x, ar[i].y);
            p.y = pack_f16x2(ar[i].z, ar[i].w);
            *(uint2*)(As + (srow + 16 * i) * LDQ + sc4) = p;
        }
#pragma unroll
        for (int i = 0; i < 4; i++) {
            uint2 p;
            p.x = pack_f16x2(br[i].x, br[i].y);
            p.y = pack_f16x2(br[i].z, br[i].w);
            *(uint2*)(Bs + (srow + 16 * i) * LDQ + sc4) = p;
        }
        __syncthreads();

        if (k0 + 64 < CDIM) {
#pragma unroll
            for (int i = 0; i < 8; i++)
                ar[i] = *(const float4*)(A + (size_t)(m0 + srow + 16 * i) * CDIM + k0 + 64 + sc4);
#pragma unroll
            for (int i = 0; i < 4; i++)
                br[i] = *(const float4*)(B + (size_t)(n0 + srow + 16 * i) * CDIM + k0 + 64 + sc4);
        }

#pragma unroll
        for (int kk = 0; kk < 4; kk++) {
            uint32_t qa[4];
            ldsm_x4(qa[0], qa[1], qa[2], qa[3],
                    smaddr(As + a_row * LDQ + 16 * kk + a_ch));
#pragma unroll
            for (int jp = 0; jp < 4; jp++) {
                uint32_t b0, b1, b2, b3;
                ldsm_x4(b0, b1, b2, b3,
                        smaddr(Bs + (16 * jp + b_row) * LDQ + 16 * kk + b_ch));
                mma16816(acc[2 * jp],     qa, b0, b1);
                mma16816(acc[2 * jp + 1], qa, b2, b3);
            }
        }
        __syncthreads();
    }

#pragma unroll
    for (int r = 0; r < 2; r++) {
#pragma unroll
        for (int j = 0; j < 8; j++) {
            const int row = m0 + 16 * warp + g + 8 * r;
            const int col = n0 + 8 * j + 2 * t;
            float x = acc[j][2 * r], y = acc[j][2 * r + 1];
            if (z == 0) {
                *(uint32_t*)(g_qh + (size_t)row * HD + col) = pack_f16x2(x * 0.125f, y * 0.125f);
            } else if (z == 1) {
                *(uint32_t*)(g_kh + (size_t)row * HD + col) = pack_f16x2(x, y);
            } else if (z == 2) {
                *(uint32_t*)(g_vh + (size_t)row * HD + col) = pack_f16x2(x, y);
            } else {
                float2 bv = *(const float2*)(bg + col);
                float2 ov;
                ov.x = 1.0f / (1.0f + __expf(-(x + bv.x)));
                ov.y = 1.0f / (1.0f + __expf(-(y + bv.y)));
                *(float2*)(g_g + (size_t)row * HD + col) = ov;
            }
        }
    }
}

// ---------------------------------------------------------------------------
// Output GEMM: out[m, n] = sum_j g_oh[m, j] * wo[n, j] + bo[n]   (A fp16)
// ---------------------------------------------------------------------------
__global__ void __launch_bounds__(256) out_gemm(const float* __restrict__ W,
                                                const float* __restrict__ bvec,
                                                float* __restrict__ outp) {
    __shared__ __half As[128 * LDQ];
    __shared__ __half Bs[64 * LDQ];

    const int m0 = blockIdx.y * 128, n0 = blockIdx.x * 64;
    const int tid = threadIdx.x;
    const int warp = tid >> 5;
    const int lane = tid & 31;
    const int g = lane >> 2, t = lane & 3;

    const int a_row = 16 * warp + (lane & 15);
    const int a_ch  = (lane >> 4) * 8;
    const int b_row = ((lane >> 4) & 1) * 8 + (lane & 7);
    const int b_ch  = ((lane >> 3) & 1) * 8;

    float acc[8][4] = {};

    for (int k0 = 0; k0 < HD; k0 += 64) {
        for (int u = tid; u < 1024; u += 256) {
            const int row = u >> 3;
            const int c8  = (u & 7) * 8;
            *(uint4*)(As + row * LDQ + c8) =
                *(const uint4*)(g_oh + (size_t)(m0 + row) * HD + k0 + c8);
        }
        for (int u = tid; u < 1024; u += 256) {
            const int row = u >> 4;
            const int c4  = (u & 15) * 4;
            float4 v = *(const float4*)(W + (size_t)(n0 + row) * HD + k0 + c4);
            uint2 p;
            p.x = pack_f16x2(v.x, v.y);
            p.y = pack_f16x2(v.z, v.w);
            *(uint2*)(Bs + row * LDQ + c4) = p;
        }
        __syncthreads();

#pragma unroll
        for (int kk = 0; kk < 4; kk++) {
            uint32_t qa[4];
            ldsm_x4(qa[0], qa[1], qa[2], qa[3],
                    smaddr(As + a_row * LDQ + 16 * kk + a_ch));
#pragma unroll
            for (int jp = 0; jp < 4; jp++) {
                uint32_t b0, b1, b2, b3;
                ldsm_x4(b0, b1, b2, b3,
                        smaddr(Bs + (16 * jp + b_row) * LDQ + 16 * kk + b_ch));
                mma16816(acc[2 * jp],     qa, b0, b1);
                mma16816(acc[2 * jp + 1], qa, b2, b3);
            }
        }
        __syncthreads();
    }

#pragma unroll
    for (int r = 0; r < 2; r++) {
#pragma unroll
        for (int j = 0; j < 8; j++) {
            const int row = m0 + 16 * warp + g + 8 * r;
            const int col = n0 + 8 * j + 2 * t;
            float2 bv = *(const float2*)(bvec + col);
            float2 ov;
            ov.x = acc[j][2 * r]     + bv.x;
            ov.y = acc[j][2 * r + 1] + bv.y;
            *(float2*)(outp + (size_t)row * CDIM + col) = ov;
        }
    }
}

// ---------------------------------------------------------------------------
// Flash attention, fp16 mma.sync, double-buffered K/V via cp.async.
// QK^T f16-accum; PV f16-accum per tile (split into two accumulators for
// error control), upconverted to persistent f32 once per tile.
// No online max: exp(s + bias) bounded. Block: 256 threads, Q=128, KV=64.
// ---------------------------------------------------------------------------
__global__ void __launch_bounds__(256, 2) attn_kernel(const float* __restrict__ bias) {
    extern __shared__ __half sm[];
    __half* Qs = sm;                         // [128][LDQ]
    __half* Ks = Qs + 128 * LDQ;             // [2][64][LDQ]
    __half* Vs = Ks + 2 * 64 * LDQ;          // [2][64][LDQ]

    const int h  = blockIdx.y;
    const int q0 = blockIdx.x * 128;
    const int tid = threadIdx.x;
    const int warp = tid >> 5;
    const int lane = tid & 31;
    const int g  = lane >> 2;
    const int t  = lane & 3;

    for (int u = tid; u < 1024; u += 256) {
        const int row = u >> 3;
        const int c8  = (u & 7) * 8;
        *(uint4*)(Qs + row * LDQ + c8) =
            *(const uint4*)(g_qh + (size_t)(q0 + row) * HD + h * DDIM + c8);
    }

    float o[8][4];
#pragma unroll
    for (int j = 0; j < 8; j++)
#pragma unroll
        for (int e = 0; e < 4; e++) o[j][e] = 0.0f;
    float lrun[2] = {0.0f, 0.0f};

    const int a_row = 16 * warp + (lane & 15);
    const int a_ch  = (lane >> 4) * 8;
    const int b_row = ((lane >> 4) & 1) * 8 + (lane & 7);
    const int b_ch  = ((lane >> 3) & 1) * 8;
    const int v_row = ((lane >> 3) & 1) * 8 + (lane & 7);
    const int v_ch  = ((lane >> 4) & 1) * 8;

    const int cp_row = tid >> 2;
    const int cp_c8  = (tid & 3) * 16;

    // Prologue: tile 0
    {
        const __half* kp = g_kh + (size_t)cp_row * HD + h * DDIM + cp_c8;
        const __half* vp = g_vh + (size_t)cp_row * HD + h * DDIM + cp_c8;
        uint32_t kd = smaddr(Ks + cp_row * LDQ + cp_c8);
        uint32_t vd = smaddr(Vs + cp_row * LDQ + cp_c8);
        cp_async16(kd, kp);           cp_async16(kd + 16, kp + 8);
        cp_async16(vd, vp);           cp_async16(vd + 16, vp + 8);
        cp_commit();
    }

    const float* bias_base = bias + (size_t)(q0 + 16 * warp + g) * NSEQ;

    for (int kt = 0; kt < NT; kt++) {
        const int buf = kt & 1;
        __half* Kb = Ks + buf * 64 * LDQ;
        __half* Vb = Vs + buf * 64 * LDQ;

        __syncthreads();

        // Prefetch tile kt+1
        if (kt + 1 < NT) {
            const int k0n = (kt + 1) * 64;
            const __half* kp = g_kh + (size_t)(k0n + cp_row) * HD + h * DDIM + cp_c8;
            const __half* vp = g_vh + (size_t)(k0n + cp_row) * HD + h * DDIM + cp_c8;
            uint32_t kd = smaddr(Ks + (buf ^ 1) * 64 * LDQ + cp_row * LDQ + cp_c8);
            uint32_t vd = smaddr(Vs + (buf ^ 1) * 64 * LDQ + cp_row * LDQ + cp_c8);
            cp_async16(kd, kp);       cp_async16(kd + 16, kp + 8);
            cp_async16(vd, vp);       cp_async16(vd + 16, vp + 8);
        }
        cp_commit();

        // Bias loads for tile kt (LDGs in flight during wait + mma)
        const int k0 = kt * 64;
        float2 bb0[8], bb1[8];
#pragma unroll
        for (int j = 0; j < 8; j++) {
            const int col = k0 + 8 * j + 2 * t;
            bb0[j] = *(const float2*)(bias_base + col);
            bb1[j] = *(const float2*)(bias_base + (size_t)8 * NSEQ + col);
        }

        cp_wait<1>();
        __syncthreads();

        // S = Q K^T  (f16 accumulate, zero-init)
        uint32_t sf[8][2];
#pragma unroll
        for (int j = 0; j < 8; j++) { sf[j][0] = 0u; sf[j][1] = 0u; }

#pragma unroll
        for (int kk = 0; kk < 4; kk++) {
            uint32_t qa[4];
            ldsm_x4(qa[0], qa[1], qa[2], qa[3],
                    smaddr(Qs + a_row * LDQ + 16 * kk + a_ch));
#pragma unroll
            for (int jp = 0; jp < 4; jp++) {
                uint32_t b0, b1, b2, b3;
                ldsm_x4(b0, b1, b2, b3,
                        smaddr(Kb + (16 * jp + b_row) * LDQ + 16 * kk + b_ch));
                mma16816_h(sf[2 * jp],     qa, b0, b1);
                mma16816_h(sf[2 * jp + 1], qa, b2, b3);
            }
        }

        // Softmax without max-subtraction; pack P directly into A-fragments
        uint32_t pa[4][4];
#pragma unroll
        for (int j = 0; j < 8; j++) {
            float2 lo = __half22float2(*(const __half2*)&sf[j][0]);   // row g
            float2 hi = __half22float2(*(const __half2*)&sf[j][1]);   // row g+8
            const float p00 = __expf(lo.x + bb0[j].x);
            const float p01 = __expf(lo.y + bb0[j].y);
            const float p10 = __expf(hi.x + bb1[j].x);
            const float p11 = __expf(hi.y + bb1[j].y);
            lrun[0] += p00 + p01;
            lrun[1] += p10 + p11;
            const int m = j >> 1;
            const int hl = j & 1;
            pa[m][2 * hl]     = pack_f16x2(p00, p01);
            pa[m][2 * hl + 1] = pack_f16x2(p10, p11);
        }

        // O += P V: per-tile f16 accumulation, split (m01 / m23), then f32 add
#pragma unroll
        for (int jp = 0; jp < 4; jp++) {
            uint32_t d0a[2] = {0u, 0u}, d1a[2] = {0u, 0u};
            uint32_t d0b[2] = {0u, 0u}, d1b[2] = {0u, 0u};
#pragma unroll
            for (int m = 0; m < 4; m++) {
                uint32_t b0, b1, b2, b3;
                ldsm_x4_t(b0, b1, b2, b3,
                          smaddr(Vb + (16 * m + v_row) * LDQ + 16 * jp + v_ch));
                if (m < 2) {
                    mma16816_h(d0a, pa[m], b0, b1);
                    mma16816_h(d1a, pa[m], b2, b3);
                } else {
                    mma16816_h(d0b, pa[m], b0, b1);
                    mma16816_h(d1b, pa[m], b2, b3);
                }
            }
            // Upconvert and accumulate into f32 (layout: reg0 = row g, reg1 = row g+8)
            float2 f;
            f = __half22float2(*(const __half2*)&d0a[0]);
            o[2 * jp][0] += f.x;  o[2 * jp][1] += f.y;
            f = __half22float2(*(const __half2*)&d0b[0]);
            o[2 * jp][0] += f.x;  o[2 * jp][1] += f.y;
            f = __half22float2(*(const __half2*)&d0a[1]);
            o[2 * jp][2] += f.x;  o[2 * jp][3] += f.y;
            f = __half22float2(*(const __half2*)&d0b[1]);
            o[2 * jp][2] += f.x;  o[2 * jp][3] += f.y;
            f = __half22float2(*(const __half2*)&d1a[0]);
            o[2 * jp + 1][0] += f.x;  o[2 * jp + 1][1] += f.y;
            f = __half22float2(*(const __half2*)&d1b[0]);
            o[2 * jp + 1][0] += f.x;  o[2 * jp + 1][1] += f.y;
            f = __half22float2(*(const __half2*)&d1a[1]);
            o[2 * jp + 1][2] += f.x;  o[2 * jp + 1][3] += f.y;
            f = __half22float2(*(const __half2*)&d1b[1]);
            o[2 * jp + 1][2] += f.x;  o[2 * jp + 1][3] += f.y;
        }
    }

    // Reduce row sums across the 4 t-lanes (once, at the end)
#pragma unroll
    for (int r = 0; r < 2; r++) {
        lrun[r] += __shfl_xor_sync(0xffffffffu, lrun[r], 1);
        lrun[r] += __shfl_xor_sync(0xffffffffu, lrun[r], 2);
    }

    // Epilogue: normalize, gate, store fp16
#pragma unroll
    for (int r = 0; r < 2; r++) {
        const float inv = 1.0f / lrun[r];
        const int row = q0 + 16 * warp + g + 8 * r;
        const size_t rb = (size_t)row * HD + h * DDIM;
#pragma unroll
        for (int j = 0; j < 8; j++) {
            const int col = 8 * j + 2 * t;
            float2 gv = *(const float2*)(g_g + rb + col);
            const float x = o[j][2 * r]     * inv * gv.x;
            const float y = o[j][2 * r + 1] * inv * gv.y;
            *(uint32_t*)(g_oh + rb + col) = pack_f16x2(x, y);
        }
    }
}

// ---------------------------------------------------------------------------
extern "C" void kernel_launch(void* const* d_in, const int* in_sizes, int n_in,
                              void* d_out, int out_size) {
    const float* q_x  = (const float*)d_in[0];
    const float* k_x  = (const float*)d_in[1];
    const float* v_x  = (const float*)d_in[2];
    const float* bias = (const float*)d_in[3];
    const float* wq   = (const float*)d_in[4];
    const float* wk   = (const float*)d_in[5];
    const float* wv   = (const float*)d_in[6];
    const float* wg   = (const float*)d_in[7];
    const float* bg   = (const float*)d_in[8];
    const float* wo   = (const float*)d_in[9];
    const float* bo   = (const float*)d_in[10];
    float* out = (float*)d_out;

    proj_all<<<dim3(HD / 64, NSEQ / 128, 4), 256>>>(q_x, k_x, v_x, wq, wk, wv, wg, bg);

    const size_t smem = (size_t)(128 + 4 * 64) * LDQ * sizeof(__half);  // 55296 B
    cudaFuncSetAttribute(attn_kernel, cudaFuncAttributeMaxDynamicSharedMemorySize, (int)smem);
    attn_kernel<<<dim3(NSEQ / 128, HEADS), 256, smem>>>(bias);

    out_gemm<<<dim3(CDIM / 64, NSEQ / 128), 256>>>(wo, bo, out);
}

// round 10
// speedup vs baseline: 1.0300x; 1.0300x over previous
#include <cuda_runtime.h>
#include <cuda_fp16.h>
#include <cstdint>

#define NSEQ 4096
#define CDIM 256
#define HEADS 8
#define DDIM 64
#define HD   512
#define LDQ  72   // fp16 smem leading dim (144B stride -> conflict-free ldmatrix)
#define NT   (NSEQ / 64)
#define UNITS_PER_HEAD 37   // 34 x 112 rows + 3 x 96 rows = 4096

// Scratch (static device arrays; no allocation allowed)
__device__ __half g_qh[NSEQ * HD];
__device__ __half g_kh[NSEQ * HD];
__device__ __half g_vh[NSEQ * HD];
__device__ float  g_g [NSEQ * HD];
__device__ __half g_oh[NSEQ * HD];

// ---------------------------------------------------------------------------
// PTX helpers
// ---------------------------------------------------------------------------
__device__ __forceinline__ uint32_t smaddr(const void* p) {
    return (uint32_t)__cvta_generic_to_shared(p);
}

__device__ __forceinline__ void ldsm_x4(uint32_t& r0, uint32_t& r1, uint32_t& r2, uint32_t& r3,
                                        uint32_t addr) {
    asm volatile("ldmatrix.sync.aligned.m8n8.x4.shared.b16 {%0,%1,%2,%3}, [%4];"
                 : "=r"(r0), "=r"(r1), "=r"(r2), "=r"(r3) : "r"(addr));
}

__device__ __forceinline__ void ldsm_x4_t(uint32_t& r0, uint32_t& r1, uint32_t& r2, uint32_t& r3,
                                          uint32_t addr) {
    asm volatile("ldmatrix.sync.aligned.m8n8.x4.trans.shared.b16 {%0,%1,%2,%3}, [%4];"
                 : "=r"(r0), "=r"(r1), "=r"(r2), "=r"(r3) : "r"(addr));
}

// f32-accumulate variant (PV + projection GEMMs)
__device__ __forceinline__ void mma16816(float* d, const uint32_t* a, uint32_t b0, uint32_t b1) {
    asm volatile(
        "mma.sync.aligned.m16n8k16.row.col.f32.f16.f16.f32 "
        "{%0,%1,%2,%3}, {%4,%5,%6,%7}, {%8,%9}, {%0,%1,%2,%3};"
        : "+f"(d[0]), "+f"(d[1]), "+f"(d[2]), "+f"(d[3])
        : "r"(a[0]), "r"(a[1]), "r"(a[2]), "r"(a[3]), "r"(b0), "r"(b1));
}

// f16-accumulate variant (QK^T only; bias added later in f32)
__device__ __forceinline__ void mma16816_h(uint32_t* d, const uint32_t* a, uint32_t b0, uint32_t b1) {
    asm volatile(
        "mma.sync.aligned.m16n8k16.row.col.f16.f16.f16.f16 "
        "{%0,%1}, {%2,%3,%4,%5}, {%6,%7}, {%0,%1};"
        : "+r"(d[0]), "+r"(d[1])
        : "r"(a[0]), "r"(a[1]), "r"(a[2]), "r"(a[3]), "r"(b0), "r"(b1));
}

// Pack two fp32 into f16x2: result = {lo=x, hi=y}
__device__ __forceinline__ uint32_t pack_f16x2(float x, float y) {
    uint32_t r;
    asm("{\n\t.reg .b16 lo, hi;\n\t"
        "cvt.rn.f16.f32 lo, %1;\n\t"
        "cvt.rn.f16.f32 hi, %2;\n\t"
        "mov.b32 %0, {lo, hi};\n\t}"
        : "=r"(r) : "f"(x), "f"(y));
    return r;
}

__device__ __forceinline__ void cp_async16(uint32_t dst, const void* src) {
    asm volatile("cp.async.cg.shared.global [%0], [%1], 16;" :: "r"(dst), "l"(src));
}
__device__ __forceinline__ void cp_commit() {
    asm volatile("cp.async.commit_group;");
}
template <int N>
__device__ __forceinline__ void cp_wait() {
    asm volatile("cp.async.wait_group %0;" :: "n"(N));
}

// ---------------------------------------------------------------------------
// Merged projection GEMMs: one launch, blockIdx.z in {0:q, 1:k, 2:v, 3:gate}
// C[m, n] = sum_c X[m, c] * W[n, c], tile M=128 x N=64, K-chunks of 64.
// Software-pipelined: LDGs for chunk k+1 in flight during mma of chunk k.
// ---------------------------------------------------------------------------
__global__ void __launch_bounds__(256) proj_all(const float* __restrict__ q_x,
                                                const float* __restrict__ k_x,
                                                const float* __restrict__ v_x,
                                                const float* __restrict__ wq,
                                                const float* __restrict__ wk,
                                                const float* __restrict__ wv,
                                                const float* __restrict__ wg,
                                                const float* __restrict__ bg) {
    __shared__ __half As[128 * LDQ];
    __shared__ __half Bs[64 * LDQ];

    const int z = blockIdx.z;
    const float* A = (z == 1) ? k_x : (z == 2) ? v_x : q_x;
    const float* B = (z == 0) ? wq : (z == 1) ? wk : (z == 2) ? wv : wg;

    const int m0 = blockIdx.y * 128, n0 = blockIdx.x * 64;
    const int tid = threadIdx.x;
    const int warp = tid >> 5;
    const int lane = tid & 31;
    const int g = lane >> 2, t = lane & 3;

    const int a_row = 16 * warp + (lane & 15);
    const int a_ch  = (lane >> 4) * 8;
    const int b_row = ((lane >> 4) & 1) * 8 + (lane & 7);
    const int b_ch  = ((lane >> 3) & 1) * 8;

    const int srow = tid >> 4;
    const int sc4  = (tid & 15) * 4;

    float acc[8][4] = {};
    float4 ar[8], br[4];

#pragma unroll
    for (int i = 0; i < 8; i++)
        ar[i] = *(const float4*)(A + (size_t)(m0 + srow + 16 * i) * CDIM + sc4);
#pragma unroll
    for (int i = 0; i < 4; i++)
        br[i] = *(const float4*)(B + (size_t)(n0 + srow + 16 * i) * CDIM + sc4);

    for (int k0 = 0; k0 < CDIM; k0 += 64) {
#pragma unroll
        for (int i = 0; i < 8; i++) {
            uint2 p;
            p.x = pack_f16x2(ar[i].x, ar[i].y);
            p.y = pack_f16x2(ar[i].z, ar[i].w);
            *(uint2*)(As + (srow + 16 * i) * LDQ + sc4) = p;
        }
#pragma unroll
        for (int i = 0; i < 4; i++) {
            uint2 p;
            p.x = pack_f16x2(br[i].x, br[i].y);
            p.y = pack_f16x2(br[i].z, br[i].w);
            *(uint2*)(Bs + (srow + 16 * i) * LDQ + sc4) = p;
        }
        __syncthreads();

        if (k0 + 64 < CDIM) {
#pragma unroll
            for (int i = 0; i < 8; i++)
                ar[i] = *(const float4*)(A + (size_t)(m0 + srow + 16 * i) * CDIM + k0 + 64 + sc4);
#pragma unroll
            for (int i = 0; i < 4; i++)
                br[i] = *(const float4*)(B + (size_t)(n0 + srow + 16 * i) * CDIM + k0 + 64 + sc4);
        }

#pragma unroll
        for (int kk = 0; kk < 4; kk++) {
            uint32_t qa[4];
            ldsm_x4(qa[0], qa[1], qa[2], qa[3],
                    smaddr(As + a_row * LDQ + 16 * kk + a_ch));
#pragma unroll
            for (int jp = 0; jp < 4; jp++) {
                uint32_t b0, b1, b2, b3;
                ldsm_x4(b0, b1, b2, b3,
                        smaddr(Bs + (16 * jp + b_row) * LDQ + 16 * kk + b_ch));
                mma16816(acc[2 * jp],     qa, b0, b1);
                mma16816(acc[2 * jp + 1], qa, b2, b3);
            }
        }
        __syncthreads();
    }

#pragma unroll
    for (int r = 0; r < 2; r++) {
#pragma unroll
        for (int j = 0; j < 8; j++) {
            const int row = m0 + 16 * warp + g + 8 * r;
            const int col = n0 + 8 * j + 2 * t;
            float x = acc[j][2 * r], y = acc[j][2 * r + 1];
            if (z == 0) {
                *(uint32_t*)(g_qh + (size_t)row * HD + col) = pack_f16x2(x * 0.125f, y * 0.125f);
            } else if (z == 1) {
                *(uint32_t*)(g_kh + (size_t)row * HD + col) = pack_f16x2(x, y);
            } else if (z == 2) {
                *(uint32_t*)(g_vh + (size_t)row * HD + col) = pack_f16x2(x, y);
            } else {
                float2 bv = *(const float2*)(bg + col);
                float2 ov;
                ov.x = 1.0f / (1.0f + __expf(-(x + bv.x)));
                ov.y = 1.0f / (1.0f + __expf(-(y + bv.y)));
                *(float2*)(g_g + (size_t)row * HD + col) = ov;
            }
        }
    }
}

// ---------------------------------------------------------------------------
// Output GEMM: out[m, n] = sum_j g_oh[m, j] * wo[n, j] + bo[n]   (A fp16)
// ---------------------------------------------------------------------------
__global__ void __launch_bounds__(256) out_gemm(const float* __restrict__ W,
                                                const float* __restrict__ bvec,
                                                float* __restrict__ outp) {
    __shared__ __half As[128 * LDQ];
    __shared__ __half Bs[64 * LDQ];

    const int m0 = blockIdx.y * 128, n0 = blockIdx.x * 64;
    const int tid = threadIdx.x;
    const int warp = tid >> 5;
    const int lane = tid & 31;
    const int g = lane >> 2, t = lane & 3;

    const int a_row = 16 * warp + (lane & 15);
    const int a_ch  = (lane >> 4) * 8;
    const int b_row = ((lane >> 4) & 1) * 8 + (lane & 7);
    const int b_ch  = ((lane >> 3) & 1) * 8;

    float acc[8][4] = {};

    for (int k0 = 0; k0 < HD; k0 += 64) {
        for (int u = tid; u < 1024; u += 256) {
            const int row = u >> 3;
            const int c8  = (u & 7) * 8;
            *(uint4*)(As + row * LDQ + c8) =
                *(const uint4*)(g_oh + (size_t)(m0 + row) * HD + k0 + c8);
        }
        for (int u = tid; u < 1024; u += 256) {
            const int row = u >> 4;
            const int c4  = (u & 15) * 4;
            float4 v = *(const float4*)(W + (size_t)(n0 + row) * HD + k0 + c4);
            uint2 p;
            p.x = pack_f16x2(v.x, v.y);
            p.y = pack_f16x2(v.z, v.w);
            *(uint2*)(Bs + row * LDQ + c4) = p;
        }
        __syncthreads();

#pragma unroll
        for (int kk = 0; kk < 4; kk++) {
            uint32_t qa[4];
            ldsm_x4(qa[0], qa[1], qa[2], qa[3],
                    smaddr(As + a_row * LDQ + 16 * kk + a_ch));
#pragma unroll
            for (int jp = 0; jp < 4; jp++) {
                uint32_t b0, b1, b2, b3;
                ldsm_x4(b0, b1, b2, b3,
                        smaddr(Bs + (16 * jp + b_row) * LDQ + 16 * kk + b_ch));
                mma16816(acc[2 * jp],     qa, b0, b1);
                mma16816(acc[2 * jp + 1], qa, b2, b3);
            }
        }
        __syncthreads();
    }

#pragma unroll
    for (int r = 0; r < 2; r++) {
#pragma unroll
        for (int j = 0; j < 8; j++) {
            const int row = m0 + 16 * warp + g + 8 * r;
            const int col = n0 + 8 * j + 2 * t;
            float2 bv = *(const float2*)(bvec + col);
            float2 ov;
            ov.x = acc[j][2 * r]     + bv.x;
            ov.y = acc[j][2 * r + 1] + bv.y;
            *(float2*)(outp + (size_t)row * CDIM + col) = ov;
        }
    }
}

// ---------------------------------------------------------------------------
// Flash attention, fp16 mma.sync, double-buffered K/V via cp.async.
// QK^T f16-accum; PV f32-accum. No online max (scores bounded).
// Grid = 296 blocks exactly (2 per SM): each head split into 37 q-units
// (34 x 112 rows + 3 x 96 rows). Warps beyond the unit's rows skip compute
// but participate in loads/barriers.
// ---------------------------------------------------------------------------
__global__ void __launch_bounds__(256, 2) attn_kernel(const float* __restrict__ bias) {
    extern __shared__ __half sm[];
    __half* Qs = sm;                         // [128][LDQ] (up to 112 used)
    __half* Ks = Qs + 128 * LDQ;             // [2][64][LDQ]
    __half* Vs = Ks + 2 * 64 * LDQ;          // [2][64][LDQ]

    const int bx   = blockIdx.x;
    const int h    = bx / UNITS_PER_HEAD;
    const int u    = bx - h * UNITS_PER_HEAD;
    const int q0   = (u < 34) ? 112 * u : 3808 + 96 * (u - 34);
    const int rows = (u < 34) ? 112 : 96;

    const int tid = threadIdx.x;
    const int warp = tid >> 5;
    const int lane = tid & 31;
    const int g  = lane >> 2;
    const int t  = lane & 3;
    const bool active = (16 * warp) < rows;

    // Load Q tile (only rows of this unit)
    for (int uu = tid; uu < 1024; uu += 256) {
        const int row = uu >> 3;
        const int c8  = (uu & 7) * 8;
        if (row < rows)
            *(uint4*)(Qs + row * LDQ + c8) =
                *(const uint4*)(g_qh + (size_t)(q0 + row) * HD + h * DDIM + c8);
    }

    float o[8][4];
#pragma unroll
    for (int j = 0; j < 8; j++)
#pragma unroll
        for (int e = 0; e < 4; e++) o[j][e] = 0.0f;
    float lrun[2] = {0.0f, 0.0f};

    const int a_row = 16 * warp + (lane & 15);
    const int a_ch  = (lane >> 4) * 8;
    const int b_row = ((lane >> 4) & 1) * 8 + (lane & 7);
    const int b_ch  = ((lane >> 3) & 1) * 8;
    const int v_row = ((lane >> 3) & 1) * 8 + (lane & 7);
    const int v_ch  = ((lane >> 4) & 1) * 8;

    const int cp_row = tid >> 2;
    const int cp_c8  = (tid & 3) * 16;

    // Prologue: K/V tile 0
    {
        const __half* kp = g_kh + (size_t)cp_row * HD + h * DDIM + cp_c8;
        const __half* vp = g_vh + (size_t)cp_row * HD + h * DDIM + cp_c8;
        uint32_t kd = smaddr(Ks + cp_row * LDQ + cp_c8);
        uint32_t vd = smaddr(Vs + cp_row * LDQ + cp_c8);
        cp_async16(kd, kp);           cp_async16(kd + 16, kp + 8);
        cp_async16(vd, vp);           cp_async16(vd + 16, vp + 8);
        cp_commit();
    }

    const float* bias_base = bias + (size_t)(q0 + 16 * warp + g) * NSEQ;

    for (int kt = 0; kt < NT; kt++) {
        const int buf = kt & 1;
        __half* Kb = Ks + buf * 64 * LDQ;
        __half* Vb = Vs + buf * 64 * LDQ;

        __syncthreads();

        // Prefetch tile kt+1
        if (kt + 1 < NT) {
            const int k0n = (kt + 1) * 64;
            const __half* kp = g_kh + (size_t)(k0n + cp_row) * HD + h * DDIM + cp_c8;
            const __half* vp = g_vh + (size_t)(k0n + cp_row) * HD + h * DDIM + cp_c8;
            uint32_t kd = smaddr(Ks + (buf ^ 1) * 64 * LDQ + cp_row * LDQ + cp_c8);
            uint32_t vd = smaddr(Vs + (buf ^ 1) * 64 * LDQ + cp_row * LDQ + cp_c8);
            cp_async16(kd, kp);       cp_async16(kd + 16, kp + 8);
            cp_async16(vd, vp);       cp_async16(vd + 16, vp + 8);
        }
        cp_commit();

        const int k0 = kt * 64;
        float2 bb0[8], bb1[8];
        if (active) {
#pragma unroll
            for (int j = 0; j < 8; j++) {
                const int col = k0 + 8 * j + 2 * t;
                bb0[j] = *(const float2*)(bias_base + col);
                bb1[j] = *(const float2*)(bias_base + (size_t)8 * NSEQ + col);
            }
        }

        cp_wait<1>();
        __syncthreads();

        if (active) {
            // S = Q K^T  (f16 accumulate, zero-init)
            uint32_t sf[8][2];
#pragma unroll
            for (int j = 0; j < 8; j++) { sf[j][0] = 0u; sf[j][1] = 0u; }

#pragma unroll
            for (int kk = 0; kk < 4; kk++) {
                uint32_t qa[4];
                ldsm_x4(qa[0], qa[1], qa[2], qa[3],
                        smaddr(Qs + a_row * LDQ + 16 * kk + a_ch));
#pragma unroll
                for (int jp = 0; jp < 4; jp++) {
                    uint32_t b0, b1, b2, b3;
                    ldsm_x4(b0, b1, b2, b3,
                            smaddr(Kb + (16 * jp + b_row) * LDQ + 16 * kk + b_ch));
                    mma16816_h(sf[2 * jp],     qa, b0, b1);
                    mma16816_h(sf[2 * jp + 1], qa, b2, b3);
                }
            }

            // Softmax without max-subtraction; pack P into A-fragments
            uint32_t pa[4][4];
#pragma unroll
            for (int j = 0; j < 8; j++) {
                float2 lo = __half22float2(*(const __half2*)&sf[j][0]);
                float2 hi = __half22float2(*(const __half2*)&sf[j][1]);
                const float p00 = __expf(lo.x + bb0[j].x);
                const float p01 = __expf(lo.y + bb0[j].y);
                const float p10 = __expf(hi.x + bb1[j].x);
                const float p11 = __expf(hi.y + bb1[j].y);
                lrun[0] += p00 + p01;
                lrun[1] += p10 + p11;
                const int m = j >> 1;
                const int hl = j & 1;
                pa[m][2 * hl]     = pack_f16x2(p00, p01);
                pa[m][2 * hl + 1] = pack_f16x2(p10, p11);
            }

            // O += P V (f32 accumulate)
#pragma unroll
            for (int m = 0; m < 4; m++) {
#pragma unroll
                for (int jp = 0; jp < 4; jp++) {
                    uint32_t b0, b1, b2, b3;
                    ldsm_x4_t(b0, b1, b2, b3,
                              smaddr(Vb + (16 * m + v_row) * LDQ + 16 * jp + v_ch));
                    mma16816(o[2 * jp],     pa[m], b0, b1);
                    mma16816(o[2 * jp + 1], pa[m], b2, b3);
                }
            }
        }
    }

    if (active) {
        // Reduce row sums across the 4 t-lanes
#pragma unroll
        for (int r = 0; r < 2; r++) {
            lrun[r] += __shfl_xor_sync(0xffffffffu, lrun[r], 1);
            lrun[r] += __shfl_xor_sync(0xffffffffu, lrun[r], 2);
        }

        // Epilogue: normalize, gate, store fp16
#pragma unroll
        for (int r = 0; r < 2; r++) {
            const float inv = 1.0f / lrun[r];
            const int row = q0 + 16 * warp + g + 8 * r;
            const size_t rb = (size_t)row * HD + h * DDIM;
#pragma unroll
            for (int j = 0; j < 8; j++) {
                const int col = 8 * j + 2 * t;
                float2 gv = *(const float2*)(g_g + rb + col);
                const float x = o[j][2 * r]     * inv * gv.x;
                const float y = o[j][2 * r + 1] * inv * gv.y;
                *(uint32_t*)(g_oh + rb + col) = pack_f16x2(x, y);
            }
        }
    }
}

// ---------------------------------------------------------------------------
extern "C" void kernel_launch(void* const* d_in, const int* in_sizes, int n_in,
                              void* d_out, int out_size) {
    const float* q_x  = (const float*)d_in[0];
    const float* k_x  = (const float*)d_in[1];
    const float* v_x  = (const float*)d_in[2];
    const float* bias = (const float*)d_in[3];
    const float* wq   = (const float*)d_in[4];
    const float* wk   = (const float*)d_in[5];
    const float* wv   = (const float*)d_in[6];
    const float* wg   = (const float*)d_in[7];
    const float* bg   = (const float*)d_in[8];
    const float* wo   = (const float*)d_in[9];
    const float* bo   = (const float*)d_in[10];
    float* out = (float*)d_out;

    proj_all<<<dim3(HD / 64, NSEQ / 128, 4), 256>>>(q_x, k_x, v_x, wq, wk, wv, wg, bg);

    const size_t smem = (size_t)(128 + 4 * 64) * LDQ * sizeof(__half);  // 55296 B
    cudaFuncSetAttribute(attn_kernel, cudaFuncAttributeMaxDynamicSharedMemorySize, (int)smem);
    attn_kernel<<<dim3(HEADS * UNITS_PER_HEAD), 256, smem>>>(bias);

    out_gemm<<<dim3(CDIM / 64, NSEQ / 128), 256>>>(wo, bo, out);
}

// round 11
// speedup vs baseline: 1.0307x; 1.0007x over previous
#include <cuda_runtime.h>
#include <cuda_fp16.h>
#include <cstdint>

#define NSEQ 4096
#define CDIM 256
#define HEADS 8
#define DDIM 64
#define HD   512
#define LDQ  72   // fp16 smem leading dim (144B stride -> conflict-free ldmatrix)
#define NT   (NSEQ / 64)

// Scratch (static device arrays; no allocation allowed)
__device__ __half g_qh[NSEQ * HD];
__device__ __half g_kh[NSEQ * HD];
__device__ __half g_vh[NSEQ * HD];
__device__ float  g_g [NSEQ * HD];
__device__ __half g_oh[NSEQ * HD];
__device__ __half g_bh[(size_t)NSEQ * NSEQ];   // bias * log2e, fp16

// ---------------------------------------------------------------------------
// PTX helpers
// ---------------------------------------------------------------------------
__device__ __forceinline__ uint32_t smaddr(const void* p) {
    return (uint32_t)__cvta_generic_to_shared(p);
}

__device__ __forceinline__ void ldsm_x4(uint32_t& r0, uint32_t& r1, uint32_t& r2, uint32_t& r3,
                                        uint32_t addr) {
    asm volatile("ldmatrix.sync.aligned.m8n8.x4.shared.b16 {%0,%1,%2,%3}, [%4];"
                 : "=r"(r0), "=r"(r1), "=r"(r2), "=r"(r3) : "r"(addr));
}

__device__ __forceinline__ void ldsm_x4_t(uint32_t& r0, uint32_t& r1, uint32_t& r2, uint32_t& r3,
                                          uint32_t addr) {
    asm volatile("ldmatrix.sync.aligned.m8n8.x4.trans.shared.b16 {%0,%1,%2,%3}, [%4];"
                 : "=r"(r0), "=r"(r1), "=r"(r2), "=r"(r3) : "r"(addr));
}

// f32-accumulate variant (PV + projection GEMMs + row sums)
__device__ __forceinline__ void mma16816(float* d, const uint32_t* a, uint32_t b0, uint32_t b1) {
    asm volatile(
        "mma.sync.aligned.m16n8k16.row.col.f32.f16.f16.f32 "
        "{%0,%1,%2,%3}, {%4,%5,%6,%7}, {%8,%9}, {%0,%1,%2,%3};"
        : "+f"(d[0]), "+f"(d[1]), "+f"(d[2]), "+f"(d[3])
        : "r"(a[0]), "r"(a[1]), "r"(a[2]), "r"(a[3]), "r"(b0), "r"(b1));
}

// f16-accumulate variant (QK^T only; bias added later)
__device__ __forceinline__ void mma16816_h(uint32_t* d, const uint32_t* a, uint32_t b0, uint32_t b1) {
    asm volatile(
        "mma.sync.aligned.m16n8k16.row.col.f16.f16.f16.f16 "
        "{%0,%1}, {%2,%3,%4,%5}, {%6,%7}, {%0,%1};"
        : "+r"(d[0]), "+r"(d[1])
        : "r"(a[0]), "r"(a[1]), "r"(a[2]), "r"(a[3]), "r"(b0), "r"(b1));
}

// Pack two fp32 into f16x2: result = {lo=x, hi=y}
__device__ __forceinline__ uint32_t pack_f16x2(float x, float y) {
    uint32_t r;
    asm("{\n\t.reg .b16 lo, hi;\n\t"
        "cvt.rn.f16.f32 lo, %1;\n\t"
        "cvt.rn.f16.f32 hi, %2;\n\t"
        "mov.b32 %0, {lo, hi};\n\t}"
        : "=r"(r) : "f"(x), "f"(y));
    return r;
}

__device__ __forceinline__ void cp_async16(uint32_t dst, const void* src) {
    asm volatile("cp.async.cg.shared.global [%0], [%1], 16;" :: "r"(dst), "l"(src));
}
__device__ __forceinline__ void cp_commit() {
    asm volatile("cp.async.commit_group;");
}
template <int N>
__device__ __forceinline__ void cp_wait() {
    asm volatile("cp.async.wait_group %0;" :: "n"(N));
}

// ---------------------------------------------------------------------------
// Merged projection GEMMs + bias conversion:
// blockIdx.z in {0:q, 1:k, 2:v, 3:gate, 4:bias->fp16*log2e}
// GEMM: C[m, n] = sum_c X[m, c] * W[n, c], tile M=128 x N=64, K-chunks of 64.
// ---------------------------------------------------------------------------
__global__ void __launch_bounds__(256) proj_all(const float* __restrict__ q_x,
                                                const float* __restrict__ k_x,
                                                const float* __restrict__ v_x,
                                                const float* __restrict__ wq,
                                                const float* __restrict__ wk,
                                                const float* __restrict__ wv,
                                                const float* __restrict__ wg,
                                                const float* __restrict__ bg,
                                                const float* __restrict__ bias) {
    const int z = blockIdx.z;

    if (z == 4) {
        // Bias conversion: 256 blocks x 65536 elems (bandwidth-bound; overlaps
        // the compute-bound GEMM blocks). g_bh = bias * log2e as fp16.
        const int idx = blockIdx.y * 8 + blockIdx.x;           // 0..255
        const size_t base = (size_t)idx * 65536;
        const float l2e = 1.44269504f;
        for (int i = threadIdx.x * 4; i < 65536; i += 1024) {
            float4 v = *(const float4*)(bias + base + i);
            uint2 p;
            p.x = pack_f16x2(v.x * l2e, v.y * l2e);
            p.y = pack_f16x2(v.z * l2e, v.w * l2e);
            *(uint2*)(g_bh + base + i) = p;
        }
        return;
    }

    __shared__ __half As[128 * LDQ];
    __shared__ __half Bs[64 * LDQ];

    const float* A = (z == 1) ? k_x : (z == 2) ? v_x : q_x;
    const float* B = (z == 0) ? wq : (z == 1) ? wk : (z == 2) ? wv : wg;

    const int m0 = blockIdx.y * 128, n0 = blockIdx.x * 64;
    const int tid = threadIdx.x;
    const int warp = tid >> 5;
    const int lane = tid & 31;
    const int g = lane >> 2, t = lane & 3;

    const int a_row = 16 * warp + (lane & 15);
    const int a_ch  = (lane >> 4) * 8;
    const int b_row = ((lane >> 4) & 1) * 8 + (lane & 7);
    const int b_ch  = ((lane >> 3) & 1) * 8;

    const int srow = tid >> 4;
    const int sc4  = (tid & 15) * 4;

    float acc[8][4] = {};
    float4 ar[8], br[4];

#pragma unroll
    for (int i = 0; i < 8; i++)
        ar[i] = *(const float4*)(A + (size_t)(m0 + srow + 16 * i) * CDIM + sc4);
#pragma unroll
    for (int i = 0; i < 4; i++)
        br[i] = *(const float4*)(B + (size_t)(n0 + srow + 16 * i) * CDIM + sc4);

    for (int k0 = 0; k0 < CDIM; k0 += 64) {
#pragma unroll
        for (int i = 0; i < 8; i++) {
            uint2 p;
            p.x = pack_f16x2(ar[i].x, ar[i].y);
            p.y = pack_f16x2(ar[i].z, ar[i].w);
            *(uint2*)(As + (srow + 16 * i) * LDQ + sc4) = p;
        }
#pragma unroll
        for (int i = 0; i < 4; i++) {
            uint2 p;
            p.x = pack_f16x2(br[i].x, br[i].y);
            p.y = pack_f16x2(br[i].z, br[i].w);
            *(uint2*)(Bs + (srow + 16 * i) * LDQ + sc4) = p;
        }
        __syncthreads();

        if (k0 + 64 < CDIM) {
#pragma unroll
            for (int i = 0; i < 8; i++)
                ar[i] = *(const float4*)(A + (size_t)(m0 + srow + 16 * i) * CDIM + k0 + 64 + sc4);
#pragma unroll
            for (int i = 0; i < 4; i++)
                br[i] = *(const float4*)(B + (size_t)(n0 + srow + 16 * i) * CDIM + k0 + 64 + sc4);
        }

#pragma unroll
        for (int kk = 0; kk < 4; kk++) {
            uint32_t qa[4];
            ldsm_x4(qa[0], qa[1], qa[2], qa[3],
                    smaddr(As + a_row * LDQ + 16 * kk + a_ch));
#pragma unroll
            for (int jp = 0; jp < 4; jp++) {
                uint32_t b0, b1, b2, b3;
                ldsm_x4(b0, b1, b2, b3,
                        smaddr(Bs + (16 * jp + b_row) * LDQ + 16 * kk + b_ch));
                mma16816(acc[2 * jp],     qa, b0, b1);
                mma16816(acc[2 * jp + 1], qa, b2, b3);
            }
        }
        __syncthreads();
    }

#pragma unroll
    for (int r = 0; r < 2; r++) {
#pragma unroll
        for (int j = 0; j < 8; j++) {
            const int row = m0 + 16 * warp + g + 8 * r;
            const int col = n0 + 8 * j + 2 * t;
            float x = acc[j][2 * r], y = acc[j][2 * r + 1];
            if (z == 0) {
                *(uint32_t*)(g_qh + (size_t)row * HD + col) = pack_f16x2(x * 0.125f, y * 0.125f);
            } else if (z == 1) {
                *(uint32_t*)(g_kh + (size_t)row * HD + col) = pack_f16x2(x, y);
            } else if (z == 2) {
                *(uint32_t*)(g_vh + (size_t)row * HD + col) = pack_f16x2(x, y);
            } else {
                float2 bv = *(const float2*)(bg + col);
                float2 ov;
                ov.x = 1.0f / (1.0f + __expf(-(x + bv.x)));
                ov.y = 1.0f / (1.0f + __expf(-(y + bv.y)));
                *(float2*)(g_g + (size_t)row * HD + col) = ov;
            }
        }
    }
}

// ---------------------------------------------------------------------------
// Output GEMM: out[m, n] = sum_j g_oh[m, j] * wo[n, j] + bo[n]   (A fp16)
// ---------------------------------------------------------------------------
__global__ void __launch_bounds__(256) out_gemm(const float* __restrict__ W,
                                                const float* __restrict__ bvec,
                                                float* __restrict__ outp) {
    __shared__ __half As[128 * LDQ];
    __shared__ __half Bs[64 * LDQ];

    const int m0 = blockIdx.y * 128, n0 = blockIdx.x * 64;
    const int tid = threadIdx.x;
    const int warp = tid >> 5;
    const int lane = tid & 31;
    const int g = lane >> 2, t = lane & 3;

    const int a_row = 16 * warp + (lane & 15);
    const int a_ch  = (lane >> 4) * 8;
    const int b_row = ((lane >> 4) & 1) * 8 + (lane & 7);
    const int b_ch  = ((lane >> 3) & 1) * 8;

    float acc[8][4] = {};

    for (int k0 = 0; k0 < HD; k0 += 64) {
        for (int u = tid; u < 1024; u += 256) {
            const int row = u >> 3;
            const int c8  = (u & 7) * 8;
            *(uint4*)(As + row * LDQ + c8) =
                *(const uint4*)(g_oh + (size_t)(m0 + row) * HD + k0 + c8);
        }
        for (int u = tid; u < 1024; u += 256) {
            const int row = u >> 4;
            const int c4  = (u & 15) * 4;
            float4 v = *(const float4*)(W + (size_t)(n0 + row) * HD + k0 + c4);
            uint2 p;
            p.x = pack_f16x2(v.x, v.y);
            p.y = pack_f16x2(v.z, v.w);
            *(uint2*)(Bs + row * LDQ + c4) = p;
        }
        __syncthreads();

#pragma unroll
        for (int kk = 0; kk < 4; kk++) {
            uint32_t qa[4];
            ldsm_x4(qa[0], qa[1], qa[2], qa[3],
                    smaddr(As + a_row * LDQ + 16 * kk + a_ch));
#pragma unroll
            for (int jp = 0; jp < 4; jp++) {
                uint32_t b0, b1, b2, b3;
                ldsm_x4(b0, b1, b2, b3,
                        smaddr(Bs + (16 * jp + b_row) * LDQ + 16 * kk + b_ch));
                mma16816(acc[2 * jp],     qa, b0, b1);
                mma16816(acc[2 * jp + 1], qa, b2, b3);
            }
        }
        __syncthreads();
    }

#pragma unroll
    for (int r = 0; r < 2; r++) {
#pragma unroll
        for (int j = 0; j < 8; j++) {
            const int row = m0 + 16 * warp + g + 8 * r;
            const int col = n0 + 8 * j + 2 * t;
            float2 bv = *(const float2*)(bvec + col);
            float2 ov;
            ov.x = acc[j][2 * r]     + bv.x;
            ov.y = acc[j][2 * r + 1] + bv.y;
            *(float2*)(outp + (size_t)row * CDIM + col) = ov;
        }
    }
}

// ---------------------------------------------------------------------------
// Flash attention, fp16 mma.sync, double-buffered K/V via cp.async.
// QK^T f16-accum; softmax entirely in f16x2 (p = 2^(s*log2e + bias*log2e),
// exp via h2exp2), producing PV A-fragments directly. Row sums via an extra
// ones-column mma into an f32 fragment. PV f32-accum. Q fragments hoisted.
// Block: 256 threads (8 warps), Q tile = 128 rows, KV tile = 64, per head.
// ---------------------------------------------------------------------------
__global__ void __launch_bounds__(256, 2) attn_kernel() {
    extern __shared__ __half sm[];
    __half* Qs = sm;                         // [128][LDQ]
    __half* Ks = Qs + 128 * LDQ;             // [2][64][LDQ]
    __half* Vs = Ks + 2 * 64 * LDQ;          // [2][64][LDQ]

    const int h  = blockIdx.y;
    const int q0 = blockIdx.x * 128;
    const int tid = threadIdx.x;
    const int warp = tid >> 5;
    const int lane = tid & 31;
    const int g  = lane >> 2;
    const int t  = lane & 3;

    for (int u = tid; u < 1024; u += 256) {
        const int row = u >> 3;
        const int c8  = (u & 7) * 8;
        *(uint4*)(Qs + row * LDQ + c8) =
            *(const uint4*)(g_qh + (size_t)(q0 + row) * HD + h * DDIM + c8);
    }

    float o[8][4];
#pragma unroll
    for (int j = 0; j < 8; j++)
#pragma unroll
        for (int e = 0; e < 4; e++) o[j][e] = 0.0f;
    float osum[4] = {0.0f, 0.0f, 0.0f, 0.0f};

    const int a_row = 16 * warp + (lane & 15);
    const int a_ch  = (lane >> 4) * 8;
    const int b_row = ((lane >> 4) & 1) * 8 + (lane & 7);
    const int b_ch  = ((lane >> 3) & 1) * 8;
    const int v_row = ((lane >> 3) & 1) * 8 + (lane & 7);
    const int v_ch  = ((lane >> 4) & 1) * 8;

    // Ones-column B fragment (col 0 = 1): constant per lane
    const uint32_t bones = (lane < 4) ? 0x3C003C00u : 0u;
    const __half2 l2e2 = __float2half2_rn(1.44269504f);

    const int cp_row = tid >> 2;
    const int cp_c8  = (tid & 3) * 16;

    // Prologue: K/V tile 0
    {
        const __half* kp = g_kh + (size_t)cp_row * HD + h * DDIM + cp_c8;
        const __half* vp = g_vh + (size_t)cp_row * HD + h * DDIM + cp_c8;
        uint32_t kd = smaddr(Ks + cp_row * LDQ + cp_c8);
        uint32_t vd = smaddr(Vs + cp_row * LDQ + cp_c8);
        cp_async16(kd, kp);           cp_async16(kd + 16, kp + 8);
        cp_async16(vd, vp);           cp_async16(vd + 16, vp + 8);
        cp_commit();
    }

    // Hoist Q fragments (Qs is stable for the whole kernel)
    __syncthreads();
    uint32_t qa[4][4];
#pragma unroll
    for (int kk = 0; kk < 4; kk++)
        ldsm_x4(qa[kk][0], qa[kk][1], qa[kk][2], qa[kk][3],
                smaddr(Qs + a_row * LDQ + 16 * kk + a_ch));

    const __half* bh_base = g_bh + (size_t)(q0 + 16 * warp + g) * NSEQ;

    for (int kt = 0; kt < NT; kt++) {
        const int buf = kt & 1;
        __half* Kb = Ks + buf * 64 * LDQ;
        __half* Vb = Vs + buf * 64 * LDQ;

        __syncthreads();

        // Prefetch tile kt+1
        if (kt + 1 < NT) {
            const int k0n = (kt + 1) * 64;
            const __half* kp = g_kh + (size_t)(k0n + cp_row) * HD + h * DDIM + cp_c8;
            const __half* vp = g_vh + (size_t)(k0n + cp_row) * HD + h * DDIM + cp_c8;
            uint32_t kd = smaddr(Ks + (buf ^ 1) * 64 * LDQ + cp_row * LDQ + cp_c8);
            uint32_t vd = smaddr(Vs + (buf ^ 1) * 64 * LDQ + cp_row * LDQ + cp_c8);
            cp_async16(kd, kp);       cp_async16(kd + 16, kp + 8);
            cp_async16(vd, vp);       cp_async16(vd + 16, vp + 8);
        }
        cp_commit();

        // Bias loads (fp16, pre-scaled by log2e), rows g and g+8
        const int k0 = kt * 64;
        uint32_t bh0[8], bh1[8];
#pragma unroll
        for (int j = 0; j < 8; j++) {
            const int col = k0 + 8 * j + 2 * t;
            bh0[j] = *(const uint32_t*)(bh_base + col);
            bh1[j] = *(const uint32_t*)(bh_base + (size_t)8 * NSEQ + col);
        }

        cp_wait<1>();
        __syncthreads();

        // S = Q K^T  (f16 accumulate, zero-init)
        uint32_t sf[8][2];
#pragma unroll
        for (int j = 0; j < 8; j++) { sf[j][0] = 0u; sf[j][1] = 0u; }

#pragma unroll
        for (int kk = 0; kk < 4; kk++) {
#pragma unroll
            for (int jp = 0; jp < 4; jp++) {
                uint32_t b0, b1, b2, b3;
                ldsm_x4(b0, b1, b2, b3,
                        smaddr(Kb + (16 * jp + b_row) * LDQ + 16 * kk + b_ch));
                mma16816_h(sf[2 * jp],     qa[kk], b0, b1);
                mma16816_h(sf[2 * jp + 1], qa[kk], b2, b3);
            }
        }

        // Softmax in f16x2: p = 2^(s*log2e + b_pre); results ARE the A-fragments
        uint32_t pa[4][4];
#pragma unroll
        for (int j = 0; j < 8; j++) {
            const int m  = j >> 1;
            const int hl = j & 1;
            __half2 a0 = __hfma2(*(const __half2*)&sf[j][0], l2e2, *(const __half2*)&bh0[j]);
            __half2 a1 = __hfma2(*(const __half2*)&sf[j][1], l2e2, *(const __half2*)&bh1[j]);
            __half2 p0 = h2exp2(a0);
            __half2 p1 = h2exp2(a1);
            pa[m][2 * hl]     = *(const uint32_t*)&p0;
            pa[m][2 * hl + 1] = *(const uint32_t*)&p1;
        }

        // O += P V (f32 accumulate) + row sums via ones-column mma
#pragma unroll
        for (int m = 0; m < 4; m++) {
#pragma unroll
            for (int jp = 0; jp < 4; jp++) {
                uint32_t b0, b1, b2, b3;
                ldsm_x4_t(b0, b1, b2, b3,
                          smaddr(Vb + (16 * m + v_row) * LDQ + 16 * jp + v_ch));
                mma16816(o[2 * jp],     pa[m], b0, b1);
                mma16816(o[2 * jp + 1], pa[m], b2, b3);
            }
            mma16816(osum, pa[m], bones, bones);
        }
    }

    // Row sums live in col 0 of the ones-mma output (lane 4g holds them)
    const float l0 = __shfl_sync(0xffffffffu, osum[0], lane & ~3);
    const float l1 = __shfl_sync(0xffffffffu, osum[2], lane & ~3);

    // Epilogue: normalize, gate, store fp16
#pragma unroll
    for (int r = 0; r < 2; r++) {
        const float inv = 1.0f / (r == 0 ? l0 : l1);
        const int row = q0 + 16 * warp + g + 8 * r;
        const size_t rb = (size_t)row * HD + h * DDIM;
#pragma unroll
        for (int j = 0; j < 8; j++) {
            const int col = 8 * j + 2 * t;
            float2 gv = *(const float2*)(g_g + rb + col);
            const float x = o[j][2 * r]     * inv * gv.x;
            const float y = o[j][2 * r + 1] * inv * gv.y;
            *(uint32_t*)(g_oh + rb + col) = pack_f16x2(x, y);
        }
    }
}

// ---------------------------------------------------------------------------
extern "C" void kernel_launch(void* const* d_in, const int* in_sizes, int n_in,
                              void* d_out, int out_size) {
    const float* q_x  = (const float*)d_in[0];
    const float* k_x  = (const float*)d_in[1];
    const float* v_x  = (const float*)d_in[2];
    const float* bias = (const float*)d_in[3];
    const float* wq   = (const float*)d_in[4];
    const float* wk   = (const float*)d_in[5];
    const float* wv   = (const float*)d_in[6];
    const float* wg   = (const float*)d_in[7];
    const float* bg   = (const float*)d_in[8];
    const float* wo   = (const float*)d_in[9];
    const float* bo   = (const float*)d_in[10];
    float* out = (float*)d_out;

    // Projections + gate + bias fp16 conversion, one launch (z = 0..4)
    proj_all<<<dim3(HD / 64, NSEQ / 128, 5), 256>>>(q_x, k_x, v_x, wq, wk, wv, wg, bg, bias);

    const size_t smem = (size_t)(128 + 4 * 64) * LDQ * sizeof(__half);  // 55296 B
    cudaFuncSetAttribute(attn_kernel, cudaFuncAttributeMaxDynamicSharedMemorySize, (int)smem);
    attn_kernel<<<dim3(NSEQ / 128, HEADS), 256, smem>>>();

    out_gemm<<<dim3(CDIM / 64, NSEQ / 128), 256>>>(wo, bo, out);
}

// round 12
// speedup vs baseline: 1.2175x; 1.1813x over previous
#include <cuda_runtime.h>
#include <cuda_fp16.h>
#include <cstdint>

#define NSEQ 4096
#define CDIM 256
#define HEADS 8
#define DDIM 64
#define HD   512
#define LDQ  72   // fp16 smem leading dim (144B stride -> conflict-free ldmatrix)
#define KVPARTS 4
#define NTP  (NSEQ / 64 / KVPARTS)   // 16 kv tiles per part

// Scratch (static device arrays; no allocation allowed)
__device__ __half g_qh[NSEQ * HD];
__device__ __half g_kh[NSEQ * HD];
__device__ __half g_vh[NSEQ * HD];
__device__ float  g_g [NSEQ * HD];
__device__ __half g_oh[NSEQ * HD];
__device__ float  g_opart[KVPARTS][NSEQ * HD];      // unnormalized O partials
__device__ float  g_ls[KVPARTS][HEADS * NSEQ];      // row-sum partials

// ---------------------------------------------------------------------------
// PTX helpers
// ---------------------------------------------------------------------------
__device__ __forceinline__ uint32_t smaddr(const void* p) {
    return (uint32_t)__cvta_generic_to_shared(p);
}

__device__ __forceinline__ void ldsm_x4(uint32_t& r0, uint32_t& r1, uint32_t& r2, uint32_t& r3,
                                        uint32_t addr) {
    asm volatile("ldmatrix.sync.aligned.m8n8.x4.shared.b16 {%0,%1,%2,%3}, [%4];"
                 : "=r"(r0), "=r"(r1), "=r"(r2), "=r"(r3) : "r"(addr));
}

__device__ __forceinline__ void ldsm_x4_t(uint32_t& r0, uint32_t& r1, uint32_t& r2, uint32_t& r3,
                                          uint32_t addr) {
    asm volatile("ldmatrix.sync.aligned.m8n8.x4.trans.shared.b16 {%0,%1,%2,%3}, [%4];"
                 : "=r"(r0), "=r"(r1), "=r"(r2), "=r"(r3) : "r"(addr));
}

// f32-accumulate variant (PV + projection GEMMs)
__device__ __forceinline__ void mma16816(float* d, const uint32_t* a, uint32_t b0, uint32_t b1) {
    asm volatile(
        "mma.sync.aligned.m16n8k16.row.col.f32.f16.f16.f32 "
        "{%0,%1,%2,%3}, {%4,%5,%6,%7}, {%8,%9}, {%0,%1,%2,%3};"
        : "+f"(d[0]), "+f"(d[1]), "+f"(d[2]), "+f"(d[3])
        : "r"(a[0]), "r"(a[1]), "r"(a[2]), "r"(a[3]), "r"(b0), "r"(b1));
}

// f16-accumulate variant (QK^T only; bias added later in f32)
__device__ __forceinline__ void mma16816_h(uint32_t* d, const uint32_t* a, uint32_t b0, uint32_t b1) {
    asm volatile(
        "mma.sync.aligned.m16n8k16.row.col.f16.f16.f16.f16 "
        "{%0,%1}, {%2,%3,%4,%5}, {%6,%7}, {%0,%1};"
        : "+r"(d[0]), "+r"(d[1])
        : "r"(a[0]), "r"(a[1]), "r"(a[2]), "r"(a[3]), "r"(b0), "r"(b1));
}

// Pack two fp32 into f16x2: result = {lo=x, hi=y}
__device__ __forceinline__ uint32_t pack_f16x2(float x, float y) {
    uint32_t r;
    asm("{\n\t.reg .b16 lo, hi;\n\t"
        "cvt.rn.f16.f32 lo, %1;\n\t"
        "cvt.rn.f16.f32 hi, %2;\n\t"
        "mov.b32 %0, {lo, hi};\n\t}"
        : "=r"(r) : "f"(x), "f"(y));
    return r;
}

__device__ __forceinline__ void cp_async16(uint32_t dst, const void* src) {
    asm volatile("cp.async.cg.shared.global [%0], [%1], 16;" :: "r"(dst), "l"(src));
}
__device__ __forceinline__ void cp_commit() {
    asm volatile("cp.async.commit_group;");
}
template <int N>
__device__ __forceinline__ void cp_wait() {
    asm volatile("cp.async.wait_group %0;" :: "n"(N));
}

// ---------------------------------------------------------------------------
// Merged projection GEMMs: one launch, blockIdx.z in {0:q, 1:k, 2:v, 3:gate}
// C[m, n] = sum_c X[m, c] * W[n, c], tile M=128 x N=64, K-chunks of 64.
// Software-pipelined: LDGs for chunk k+1 in flight during mma of chunk k.
// ---------------------------------------------------------------------------
__global__ void __launch_bounds__(256) proj_all(const float* __restrict__ q_x,
                                                const float* __restrict__ k_x,
                                                const float* __restrict__ v_x,
                                                const float* __restrict__ wq,
                                                const float* __restrict__ wk,
                                                const float* __restrict__ wv,
                                                const float* __restrict__ wg,
                                                const float* __restrict__ bg) {
    __shared__ __half As[128 * LDQ];
    __shared__ __half Bs[64 * LDQ];

    const int z = blockIdx.z;
    const float* A = (z == 1) ? k_x : (z == 2) ? v_x : q_x;
    const float* B = (z == 0) ? wq : (z == 1) ? wk : (z == 2) ? wv : wg;

    const int m0 = blockIdx.y * 128, n0 = blockIdx.x * 64;
    const int tid = threadIdx.x;
    const int warp = tid >> 5;
    const int lane = tid & 31;
    const int g = lane >> 2, t = lane & 3;

    const int a_row = 16 * warp + (lane & 15);
    const int a_ch  = (lane >> 4) * 8;
    const int b_row = ((lane >> 4) & 1) * 8 + (lane & 7);
    const int b_ch  = ((lane >> 3) & 1) * 8;

    const int srow = tid >> 4;
    const int sc4  = (tid & 15) * 4;

    float acc[8][4] = {};
    float4 ar[8], br[4];

#pragma unroll
    for (int i = 0; i < 8; i++)
        ar[i] = *(const float4*)(A + (size_t)(m0 + srow + 16 * i) * CDIM + sc4);
#pragma unroll
    for (int i = 0; i < 4; i++)
        br[i] = *(const float4*)(B + (size_t)(n0 + srow + 16 * i) * CDIM + sc4);

    for (int k0 = 0; k0 < CDIM; k0 += 64) {
#pragma unroll
        for (int i = 0; i < 8; i++) {
            uint2 p;
            p.x = pack_f16x2(ar[i].x, ar[i].y);
            p.y = pack_f16x2(ar[i].z, ar[i].w);
            *(uint2*)(As + (srow + 16 * i) * LDQ + sc4) = p;
        }
#pragma unroll
        for (int i = 0; i < 4; i++) {
            uint2 p;
            p.x = pack_f16x2(br[i].x, br[i].y);
            p.y = pack_f16x2(br[i].z, br[i].w);
            *(uint2*)(Bs + (srow + 16 * i) * LDQ + sc4) = p;
        }
        __syncthreads();

        if (k0 + 64 < CDIM) {
#pragma unroll
            for (int i = 0; i < 8; i++)
                ar[i] = *(const float4*)(A + (size_t)(m0 + srow + 16 * i) * CDIM + k0 + 64 + sc4);
#pragma unroll
            for (int i = 0; i < 4; i++)
                br[i] = *(const float4*)(B + (size_t)(n0 + srow + 16 * i) * CDIM + k0 + 64 + sc4);
        }

#pragma unroll
        for (int kk = 0; kk < 4; kk++) {
            uint32_t qa[4];
            ldsm_x4(qa[0], qa[1], qa[2], qa[3],
                    smaddr(As + a_row * LDQ + 16 * kk + a_ch));
#pragma unroll
            for (int jp = 0; jp < 4; jp++) {
                uint32_t b0, b1, b2, b3;
                ldsm_x4(b0, b1, b2, b3,
                        smaddr(Bs + (16 * jp + b_row) * LDQ + 16 * kk + b_ch));
                mma16816(acc[2 * jp],     qa, b0, b1);
                mma16816(acc[2 * jp + 1], qa, b2, b3);
            }
        }
        __syncthreads();
    }

#pragma unroll
    for (int r = 0; r < 2; r++) {
#pragma unroll
        for (int j = 0; j < 8; j++) {
            const int row = m0 + 16 * warp + g + 8 * r;
            const int col = n0 + 8 * j + 2 * t;
            float x = acc[j][2 * r], y = acc[j][2 * r + 1];
            if (z == 0) {
                *(uint32_t*)(g_qh + (size_t)row * HD + col) = pack_f16x2(x * 0.125f, y * 0.125f);
            } else if (z == 1) {
                *(uint32_t*)(g_kh + (size_t)row * HD + col) = pack_f16x2(x, y);
            } else if (z == 2) {
                *(uint32_t*)(g_vh + (size_t)row * HD + col) = pack_f16x2(x, y);
            } else {
                float2 bv = *(const float2*)(bg + col);
                float2 ov;
                ov.x = 1.0f / (1.0f + __expf(-(x + bv.x)));
                ov.y = 1.0f / (1.0f + __expf(-(y + bv.y)));
                *(float2*)(g_g + (size_t)row * HD + col) = ov;
            }
        }
    }
}

// ---------------------------------------------------------------------------
// Output GEMM: out[m, n] = sum_j g_oh[m, j] * wo[n, j] + bo[n]   (A fp16)
// ---------------------------------------------------------------------------
__global__ void __launch_bounds__(256) out_gemm(const float* __restrict__ W,
                                                const float* __restrict__ bvec,
                                                float* __restrict__ outp) {
    __shared__ __half As[128 * LDQ];
    __shared__ __half Bs[64 * LDQ];

    const int m0 = blockIdx.y * 128, n0 = blockIdx.x * 64;
    const int tid = threadIdx.x;
    const int warp = tid >> 5;
    const int lane = tid & 31;
    const int g = lane >> 2, t = lane & 3;

    const int a_row = 16 * warp + (lane & 15);
    const int a_ch  = (lane >> 4) * 8;
    const int b_row = ((lane >> 4) & 1) * 8 + (lane & 7);
    const int b_ch  = ((lane >> 3) & 1) * 8;

    float acc[8][4] = {};

    for (int k0 = 0; k0 < HD; k0 += 64) {
        for (int u = tid; u < 1024; u += 256) {
            const int row = u >> 3;
            const int c8  = (u & 7) * 8;
            *(uint4*)(As + row * LDQ + c8) =
                *(const uint4*)(g_oh + (size_t)(m0 + row) * HD + k0 + c8);
        }
        for (int u = tid; u < 1024; u += 256) {
            const int row = u >> 4;
            const int c4  = (u & 15) * 4;
            float4 v = *(const float4*)(W + (size_t)(n0 + row) * HD + k0 + c4);
            uint2 p;
            p.x = pack_f16x2(v.x, v.y);
            p.y = pack_f16x2(v.z, v.w);
            *(uint2*)(Bs + row * LDQ + c4) = p;
        }
        __syncthreads();

#pragma unroll
        for (int kk = 0; kk < 4; kk++) {
            uint32_t qa[4];
            ldsm_x4(qa[0], qa[1], qa[2], qa[3],
                    smaddr(As + a_row * LDQ + 16 * kk + a_ch));
#pragma unroll
            for (int jp = 0; jp < 4; jp++) {
                uint32_t b0, b1, b2, b3;
                ldsm_x4(b0, b1, b2, b3,
                        smaddr(Bs + (16 * jp + b_row) * LDQ + 16 * kk + b_ch));
                mma16816(acc[2 * jp],     qa, b0, b1);
                mma16816(acc[2 * jp + 1], qa, b2, b3);
            }
        }
        __syncthreads();
    }

#pragma unroll
    for (int r = 0; r < 2; r++) {
#pragma unroll
        for (int j = 0; j < 8; j++) {
            const int row = m0 + 16 * warp + g + 8 * r;
            const int col = n0 + 8 * j + 2 * t;
            float2 bv = *(const float2*)(bvec + col);
            float2 ov;
            ov.x = acc[j][2 * r]     + bv.x;
            ov.y = acc[j][2 * r + 1] + bv.y;
            *(float2*)(outp + (size_t)row * CDIM + col) = ov;
        }
    }
}

// ---------------------------------------------------------------------------
// Split-KV flash attention. Grid (32 q-tiles, 8 heads, 4 kv-parts) = 1024
// equal blocks -> per-SM tensor quantum shrinks 4x (max 7 block-works/SM vs
// 2x107us before). No-max softmax is linear over kv, so partials (O_unnorm,
// rowsum) just add in the combine kernel. QK f16-accum, PV f32-accum,
// fp32 bias + softmax (round-8 numerics). Q fragments hoisted.
// ---------------------------------------------------------------------------
__global__ void __launch_bounds__(256, 2) attn_kernel(const float* __restrict__ bias) {
    extern __shared__ __half sm[];
    __half* Qs = sm;                         // [128][LDQ]
    __half* Ks = Qs + 128 * LDQ;             // [2][64][LDQ]
    __half* Vs = Ks + 2 * 64 * LDQ;          // [2][64][LDQ]

    const int h    = blockIdx.y;
    const int q0   = blockIdx.x * 128;
    const int part = blockIdx.z;
    const int kvb  = part * (NSEQ / KVPARTS);   // kv base for this part

    const int tid = threadIdx.x;
    const int warp = tid >> 5;
    const int lane = tid & 31;
    const int g  = lane >> 2;
    const int t  = lane & 3;

    for (int u = tid; u < 1024; u += 256) {
        const int row = u >> 3;
        const int c8  = (u & 7) * 8;
        *(uint4*)(Qs + row * LDQ + c8) =
            *(const uint4*)(g_qh + (size_t)(q0 + row) * HD + h * DDIM + c8);
    }

    float o[8][4];
#pragma unroll
    for (int j = 0; j < 8; j++)
#pragma unroll
        for (int e = 0; e < 4; e++) o[j][e] = 0.0f;
    float lrun[2] = {0.0f, 0.0f};

    const int a_row = 16 * warp + (lane & 15);
    const int a_ch  = (lane >> 4) * 8;
    const int b_row = ((lane >> 4) & 1) * 8 + (lane & 7);
    const int b_ch  = ((lane >> 3) & 1) * 8;
    const int v_row = ((lane >> 3) & 1) * 8 + (lane & 7);
    const int v_ch  = ((lane >> 4) & 1) * 8;

    const int cp_row = tid >> 2;
    const int cp_c8  = (tid & 3) * 16;

    // Prologue: K/V tile 0 of this part
    {
        const __half* kp = g_kh + (size_t)(kvb + cp_row) * HD + h * DDIM + cp_c8;
        const __half* vp = g_vh + (size_t)(kvb + cp_row) * HD + h * DDIM + cp_c8;
        uint32_t kd = smaddr(Ks + cp_row * LDQ + cp_c8);
        uint32_t vd = smaddr(Vs + cp_row * LDQ + cp_c8);
        cp_async16(kd, kp);           cp_async16(kd + 16, kp + 8);
        cp_async16(vd, vp);           cp_async16(vd + 16, vp + 8);
        cp_commit();
    }

    // Hoist Q fragments (Qs stable once loaded)
    __syncthreads();
    uint32_t qa[4][4];
#pragma unroll
    for (int kk = 0; kk < 4; kk++)
        ldsm_x4(qa[kk][0], qa[kk][1], qa[kk][2], qa[kk][3],
                smaddr(Qs + a_row * LDQ + 16 * kk + a_ch));

    const float* bias_base = bias + (size_t)(q0 + 16 * warp + g) * NSEQ;

    for (int kt = 0; kt < NTP; kt++) {
        const int buf = kt & 1;
        __half* Kb = Ks + buf * 64 * LDQ;
        __half* Vb = Vs + buf * 64 * LDQ;

        __syncthreads();

        // Prefetch tile kt+1
        if (kt + 1 < NTP) {
            const int k0n = kvb + (kt + 1) * 64;
            const __half* kp = g_kh + (size_t)(k0n + cp_row) * HD + h * DDIM + cp_c8;
            const __half* vp = g_vh + (size_t)(k0n + cp_row) * HD + h * DDIM + cp_c8;
            uint32_t kd = smaddr(Ks + (buf ^ 1) * 64 * LDQ + cp_row * LDQ + cp_c8);
            uint32_t vd = smaddr(Vs + (buf ^ 1) * 64 * LDQ + cp_row * LDQ + cp_c8);
            cp_async16(kd, kp);       cp_async16(kd + 16, kp + 8);
            cp_async16(vd, vp);       cp_async16(vd + 16, vp + 8);
        }
        cp_commit();

        // Bias loads for tile kt (fp32; LDGs in flight during wait + mma)
        const int k0 = kvb + kt * 64;
        float2 bb0[8], bb1[8];
#pragma unroll
        for (int j = 0; j < 8; j++) {
            const int col = k0 + 8 * j + 2 * t;
            bb0[j] = *(const float2*)(bias_base + col);
            bb1[j] = *(const float2*)(bias_base + (size_t)8 * NSEQ + col);
        }

        cp_wait<1>();
        __syncthreads();

        // S = Q K^T  (f16 accumulate, zero-init)
        uint32_t sf[8][2];
#pragma unroll
        for (int j = 0; j < 8; j++) { sf[j][0] = 0u; sf[j][1] = 0u; }

#pragma unroll
        for (int kk = 0; kk < 4; kk++) {
#pragma unroll
            for (int jp = 0; jp < 4; jp++) {
                uint32_t b0, b1, b2, b3;
                ldsm_x4(b0, b1, b2, b3,
                        smaddr(Kb + (16 * jp + b_row) * LDQ + 16 * kk + b_ch));
                mma16816_h(sf[2 * jp],     qa[kk], b0, b1);
                mma16816_h(sf[2 * jp + 1], qa[kk], b2, b3);
            }
        }

        // Softmax without max-subtraction; pack P into A-fragments
        uint32_t pa[4][4];
#pragma unroll
        for (int j = 0; j < 8; j++) {
            float2 lo = __half22float2(*(const __half2*)&sf[j][0]);
            float2 hi = __half22float2(*(const __half2*)&sf[j][1]);
            const float p00 = __expf(lo.x + bb0[j].x);
            const float p01 = __expf(lo.y + bb0[j].y);
            const float p10 = __expf(hi.x + bb1[j].x);
            const float p11 = __expf(hi.y + bb1[j].y);
            lrun[0] += p00 + p01;
            lrun[1] += p10 + p11;
            const int m = j >> 1;
            const int hl = j & 1;
            pa[m][2 * hl]     = pack_f16x2(p00, p01);
            pa[m][2 * hl + 1] = pack_f16x2(p10, p11);
        }

        // O += P V (f32 accumulate)
#pragma unroll
        for (int m = 0; m < 4; m++) {
#pragma unroll
            for (int jp = 0; jp < 4; jp++) {
                uint32_t b0, b1, b2, b3;
                ldsm_x4_t(b0, b1, b2, b3,
                          smaddr(Vb + (16 * m + v_row) * LDQ + 16 * jp + v_ch));
                mma16816(o[2 * jp],     pa[m], b0, b1);
                mma16816(o[2 * jp + 1], pa[m], b2, b3);
            }
        }
    }

    // Reduce row sums across the 4 t-lanes
#pragma unroll
    for (int r = 0; r < 2; r++) {
        lrun[r] += __shfl_xor_sync(0xffffffffu, lrun[r], 1);
        lrun[r] += __shfl_xor_sync(0xffffffffu, lrun[r], 2);
    }

    // Epilogue: write unnormalized f32 partials + row sums for this part
    float* opart = g_opart[part];
#pragma unroll
    for (int r = 0; r < 2; r++) {
        const int row = q0 + 16 * warp + g + 8 * r;
        if (t == 0)
            g_ls[part][h * NSEQ + row] = lrun[r];
        const size_t rb = (size_t)row * HD + h * DDIM;
#pragma unroll
        for (int j = 0; j < 8; j++) {
            const int col = 8 * j + 2 * t;
            float2 ov;
            ov.x = o[j][2 * r];
            ov.y = o[j][2 * r + 1];
            *(float2*)(opart + rb + col) = ov;
        }
    }
}

// ---------------------------------------------------------------------------
// Combine: sum the 4 kv-part partials, normalize, gate, store fp16 g_oh.
// ---------------------------------------------------------------------------
__global__ void __launch_bounds__(256) combine_kernel() {
    const size_t idx = ((size_t)blockIdx.x * 256 + threadIdx.x) * 4;
    const int row = (int)(idx / HD);
    const int col = (int)(idx % HD);
    const int h   = col / DDIM;

    float4 s = *(const float4*)(g_opart[0] + idx);
    float4 s1 = *(const float4*)(g_opart[1] + idx);
    float4 s2 = *(const float4*)(g_opart[2] + idx);
    float4 s3 = *(const float4*)(g_opart[3] + idx);
    s.x += s1.x + s2.x + s3.x;
    s.y += s1.y + s2.y + s3.y;
    s.z += s1.z + s2.z + s3.z;
    s.w += s1.w + s2.w + s3.w;

    const int li = h * NSEQ + row;
    const float l = g_ls[0][li] + g_ls[1][li] + g_ls[2][li] + g_ls[3][li];
    const float inv = 1.0f / l;

    float4 gv = *(const float4*)(g_g + idx);
    uint2 p;
    p.x = pack_f16x2(s.x * inv * gv.x, s.y * inv * gv.y);
    p.y = pack_f16x2(s.z * inv * gv.z, s.w * inv * gv.w);
    *(uint2*)(g_oh + idx) = p;
}

// ---------------------------------------------------------------------------
extern "C" void kernel_launch(void* const* d_in, const int* in_sizes, int n_in,
                              void* d_out, int out_size) {
    const float* q_x  = (const float*)d_in[0];
    const float* k_x  = (const float*)d_in[1];
    const float* v_x  = (const float*)d_in[2];
    const float* bias = (const float*)d_in[3];
    const float* wq   = (const float*)d_in[4];
    const float* wk   = (const float*)d_in[5];
    const float* wv   = (const float*)d_in[6];
    const float* wg   = (const float*)d_in[7];
    const float* bg   = (const float*)d_in[8];
    const float* wo   = (const float*)d_in[9];
    const float* bo   = (const float*)d_in[10];
    float* out = (float*)d_out;

    proj_all<<<dim3(HD / 64, NSEQ / 128, 4), 256>>>(q_x, k_x, v_x, wq, wk, wv, wg, bg);

    const size_t smem = (size_t)(128 + 4 * 64) * LDQ * sizeof(__half);  // 55296 B
    cudaFuncSetAttribute(attn_kernel, cudaFuncAttributeMaxDynamicSharedMemorySize, (int)smem);
    attn_kernel<<<dim3(NSEQ / 128, HEADS, KVPARTS), 256, smem>>>(bias);

    combine_kernel<<<(NSEQ * HD) / 1024, 256>>>();

    out_gemm<<<dim3(CDIM / 64, NSEQ / 128), 256>>>(wo, bo, out);
}

// round 13
// speedup vs baseline: 1.3288x; 1.0914x over previous
#include <cuda_runtime.h>
#include <cuda_fp16.h>
#include <cstdint>

#define NSEQ 4096
#define CDIM 256
#define HEADS 8
#define DDIM 64
#define HD   512
#define LDQ  72   // fp16 smem leading dim (144B stride -> conflict-free ldmatrix)
#define KVPARTS 4
#define NTP  (NSEQ / 64 / KVPARTS)   // 16 kv tiles per part

// Scratch (static device arrays; no allocation allowed)
__device__ __half g_qh[NSEQ * HD];
__device__ __half g_kh[NSEQ * HD];
__device__ __half g_vh[NSEQ * HD];
__device__ float  g_g [NSEQ * HD];
__device__ __half g_oh[NSEQ * HD];
__device__ float  g_opart[KVPARTS][NSEQ * HD];      // unnormalized O partials
__device__ float  g_ls[KVPARTS][HEADS * NSEQ];      // row-sum partials

// ---------------------------------------------------------------------------
// PTX helpers
// ---------------------------------------------------------------------------
__device__ __forceinline__ uint32_t smaddr(const void* p) {
    return (uint32_t)__cvta_generic_to_shared(p);
}

__device__ __forceinline__ void ldsm_x4(uint32_t& r0, uint32_t& r1, uint32_t& r2, uint32_t& r3,
                                        uint32_t addr) {
    asm volatile("ldmatrix.sync.aligned.m8n8.x4.shared.b16 {%0,%1,%2,%3}, [%4];"
                 : "=r"(r0), "=r"(r1), "=r"(r2), "=r"(r3) : "r"(addr));
}

__device__ __forceinline__ void ldsm_x4_t(uint32_t& r0, uint32_t& r1, uint32_t& r2, uint32_t& r3,
                                          uint32_t addr) {
    asm volatile("ldmatrix.sync.aligned.m8n8.x4.trans.shared.b16 {%0,%1,%2,%3}, [%4];"
                 : "=r"(r0), "=r"(r1), "=r"(r2), "=r"(r3) : "r"(addr));
}

// f32-accumulate variant (PV + projection GEMMs)
__device__ __forceinline__ void mma16816(float* d, const uint32_t* a, uint32_t b0, uint32_t b1) {
    asm volatile(
        "mma.sync.aligned.m16n8k16.row.col.f32.f16.f16.f32 "
        "{%0,%1,%2,%3}, {%4,%5,%6,%7}, {%8,%9}, {%0,%1,%2,%3};"
        : "+f"(d[0]), "+f"(d[1]), "+f"(d[2]), "+f"(d[3])
        : "r"(a[0]), "r"(a[1]), "r"(a[2]), "r"(a[3]), "r"(b0), "r"(b1));
}

// f16-accumulate variant (QK^T only; bias added later in f32)
__device__ __forceinline__ void mma16816_h(uint32_t* d, const uint32_t* a, uint32_t b0, uint32_t b1) {
    asm volatile(
        "mma.sync.aligned.m16n8k16.row.col.f16.f16.f16.f16 "
        "{%0,%1}, {%2,%3,%4,%5}, {%6,%7}, {%0,%1};"
        : "+r"(d[0]), "+r"(d[1])
        : "r"(a[0]), "r"(a[1]), "r"(a[2]), "r"(a[3]), "r"(b0), "r"(b1));
}

// Pack two fp32 into f16x2: result = {lo=x, hi=y}
__device__ __forceinline__ uint32_t pack_f16x2(float x, float y) {
    uint32_t r;
    asm("{\n\t.reg .b16 lo, hi;\n\t"
        "cvt.rn.f16.f32 lo, %1;\n\t"
        "cvt.rn.f16.f32 hi, %2;\n\t"
        "mov.b32 %0, {lo, hi};\n\t}"
        : "=r"(r) : "f"(x), "f"(y));
    return r;
}

__device__ __forceinline__ void cp_async16(uint32_t dst, const void* src) {
    asm volatile("cp.async.cg.shared.global [%0], [%1], 16;" :: "r"(dst), "l"(src));
}
__device__ __forceinline__ void cp_commit() {
    asm volatile("cp.async.commit_group;");
}
template <int N>
__device__ __forceinline__ void cp_wait() {
    asm volatile("cp.async.wait_group %0;" :: "n"(N));
}

// ---------------------------------------------------------------------------
// Merged projection GEMMs: one launch, blockIdx.z in {0:q, 1:k, 2:v, 3:gate}
// C[m, n] = sum_c X[m, c] * W[n, c], tile M=128 x N=64, K-chunks of 64.
// Software-pipelined: LDGs for chunk k+1 in flight during mma of chunk k.
// ---------------------------------------------------------------------------
__global__ void __launch_bounds__(256) proj_all(const float* __restrict__ q_x,
                                                const float* __restrict__ k_x,
                                                const float* __restrict__ v_x,
                                                const float* __restrict__ wq,
                                                const float* __restrict__ wk,
                                                const float* __restrict__ wv,
                                                const float* __restrict__ wg,
                                                const float* __restrict__ bg) {
    __shared__ __half As[128 * LDQ];
    __shared__ __half Bs[64 * LDQ];

    const int z = blockIdx.z;
    const float* A = (z == 1) ? k_x : (z == 2) ? v_x : q_x;
    const float* B = (z == 0) ? wq : (z == 1) ? wk : (z == 2) ? wv : wg;

    const int m0 = blockIdx.y * 128, n0 = blockIdx.x * 64;
    const int tid = threadIdx.x;
    const int warp = tid >> 5;
    const int lane = tid & 31;
    const int g = lane >> 2, t = lane & 3;

    const int a_row = 16 * warp + (lane & 15);
    const int a_ch  = (lane >> 4) * 8;
    const int b_row = ((lane >> 4) & 1) * 8 + (lane & 7);
    const int b_ch  = ((lane >> 3) & 1) * 8;

    const int srow = tid >> 4;
    const int sc4  = (tid & 15) * 4;

    float acc[8][4] = {};
    float4 ar[8], br[4];

#pragma unroll
    for (int i = 0; i < 8; i++)
        ar[i] = *(const float4*)(A + (size_t)(m0 + srow + 16 * i) * CDIM + sc4);
#pragma unroll
    for (int i = 0; i < 4; i++)
        br[i] = *(const float4*)(B + (size_t)(n0 + srow + 16 * i) * CDIM + sc4);

    for (int k0 = 0; k0 < CDIM; k0 += 64) {
#pragma unroll
        for (int i = 0; i < 8; i++) {
            uint2 p;
            p.x = pack_f16x2(ar[i].x, ar[i].y);
            p.y = pack_f16x2(ar[i].z, ar[i].w);
            *(uint2*)(As + (srow + 16 * i) * LDQ + sc4) = p;
        }
#pragma unroll
        for (int i = 0; i < 4; i++) {
            uint2 p;
            p.x = pack_f16x2(br[i].x, br[i].y);
            p.y = pack_f16x2(br[i].z, br[i].w);
            *(uint2*)(Bs + (srow + 16 * i) * LDQ + sc4) = p;
        }
        __syncthreads();

        if (k0 + 64 < CDIM) {
#pragma unroll
            for (int i = 0; i < 8; i++)
                ar[i] = *(const float4*)(A + (size_t)(m0 + srow + 16 * i) * CDIM + k0 + 64 + sc4);
#pragma unroll
            for (int i = 0; i < 4; i++)
                br[i] = *(const float4*)(B + (size_t)(n0 + srow + 16 * i) * CDIM + k0 + 64 + sc4);
        }

#pragma unroll
        for (int kk = 0; kk < 4; kk++) {
            uint32_t qa[4];
            ldsm_x4(qa[0], qa[1], qa[2], qa[3],
                    smaddr(As + a_row * LDQ + 16 * kk + a_ch));
#pragma unroll
            for (int jp = 0; jp < 4; jp++) {
                uint32_t b0, b1, b2, b3;
                ldsm_x4(b0, b1, b2, b3,
                        smaddr(Bs + (16 * jp + b_row) * LDQ + 16 * kk + b_ch));
                mma16816(acc[2 * jp],     qa, b0, b1);
                mma16816(acc[2 * jp + 1], qa, b2, b3);
            }
        }
        __syncthreads();
    }

#pragma unroll
    for (int r = 0; r < 2; r++) {
#pragma unroll
        for (int j = 0; j < 8; j++) {
            const int row = m0 + 16 * warp + g + 8 * r;
            const int col = n0 + 8 * j + 2 * t;
            float x = acc[j][2 * r], y = acc[j][2 * r + 1];
            if (z == 0) {
                *(uint32_t*)(g_qh + (size_t)row * HD + col) = pack_f16x2(x * 0.125f, y * 0.125f);
            } else if (z == 1) {
                *(uint32_t*)(g_kh + (size_t)row * HD + col) = pack_f16x2(x, y);
            } else if (z == 2) {
                *(uint32_t*)(g_vh + (size_t)row * HD + col) = pack_f16x2(x, y);
            } else {
                float2 bv = *(const float2*)(bg + col);
                float2 ov;
                ov.x = 1.0f / (1.0f + __expf(-(x + bv.x)));
                ov.y = 1.0f / (1.0f + __expf(-(y + bv.y)));
                *(float2*)(g_g + (size_t)row * HD + col) = ov;
            }
        }
    }
}

// ---------------------------------------------------------------------------
// Output GEMM: out[m, n] = sum_j g_oh[m, j] * wo[n, j] + bo[n]   (A fp16)
// Register-staged pipeline over 8 K-chunks (A uint4 raw, B fp32->f16).
// ---------------------------------------------------------------------------
__global__ void __launch_bounds__(256) out_gemm(const float* __restrict__ W,
                                                const float* __restrict__ bvec,
                                                float* __restrict__ outp) {
    __shared__ __half As[128 * LDQ];
    __shared__ __half Bs[64 * LDQ];

    const int m0 = blockIdx.y * 128, n0 = blockIdx.x * 64;
    const int tid = threadIdx.x;
    const int warp = tid >> 5;
    const int lane = tid & 31;
    const int g = lane >> 2, t = lane & 3;

    const int a_row = 16 * warp + (lane & 15);
    const int a_ch  = (lane >> 4) * 8;
    const int b_row = ((lane >> 4) & 1) * 8 + (lane & 7);
    const int b_ch  = ((lane >> 3) & 1) * 8;

    // A staging: 4 uint4 per thread (rows tid>>3 + 32i, col chunk (tid&7)*8)
    const int arow_s = tid >> 3;
    const int ac8    = (tid & 7) * 8;
    // B staging: 4 float4 per thread (rows tid>>4 + 16i, cols (tid&15)*4)
    const int brow_s = tid >> 4;
    const int bc4    = (tid & 15) * 4;

    float acc[8][4] = {};
    uint4  ar[4];
    float4 br[4];

#pragma unroll
    for (int i = 0; i < 4; i++)
        ar[i] = *(const uint4*)(g_oh + (size_t)(m0 + arow_s + 32 * i) * HD + ac8);
#pragma unroll
    for (int i = 0; i < 4; i++)
        br[i] = *(const float4*)(W + (size_t)(n0 + brow_s + 16 * i) * HD + bc4);

    for (int k0 = 0; k0 < HD; k0 += 64) {
#pragma unroll
        for (int i = 0; i < 4; i++)
            *(uint4*)(As + (arow_s + 32 * i) * LDQ + ac8) = ar[i];
#pragma unroll
        for (int i = 0; i < 4; i++) {
            uint2 p;
            p.x = pack_f16x2(br[i].x, br[i].y);
            p.y = pack_f16x2(br[i].z, br[i].w);
            *(uint2*)(Bs + (brow_s + 16 * i) * LDQ + bc4) = p;
        }
        __syncthreads();

        if (k0 + 64 < HD) {
#pragma unroll
            for (int i = 0; i < 4; i++)
                ar[i] = *(const uint4*)(g_oh + (size_t)(m0 + arow_s + 32 * i) * HD + k0 + 64 + ac8);
#pragma unroll
            for (int i = 0; i < 4; i++)
                br[i] = *(const float4*)(W + (size_t)(n0 + brow_s + 16 * i) * HD + k0 + 64 + bc4);
        }

#pragma unroll
        for (int kk = 0; kk < 4; kk++) {
            uint32_t qa[4];
            ldsm_x4(qa[0], qa[1], qa[2], qa[3],
                    smaddr(As + a_row * LDQ + 16 * kk + a_ch));
#pragma unroll
            for (int jp = 0; jp < 4; jp++) {
                uint32_t b0, b1, b2, b3;
                ldsm_x4(b0, b1, b2, b3,
                        smaddr(Bs + (16 * jp + b_row) * LDQ + 16 * kk + b_ch));
                mma16816(acc[2 * jp],     qa, b0, b1);
                mma16816(acc[2 * jp + 1], qa, b2, b3);
            }
        }
        __syncthreads();
    }

#pragma unroll
    for (int r = 0; r < 2; r++) {
#pragma unroll
        for (int j = 0; j < 8; j++) {
            const int row = m0 + 16 * warp + g + 8 * r;
            const int col = n0 + 8 * j + 2 * t;
            float2 bv = *(const float2*)(bvec + col);
            float2 ov;
            ov.x = acc[j][2 * r]     + bv.x;
            ov.y = acc[j][2 * r + 1] + bv.y;
            *(float2*)(outp + (size_t)row * CDIM + col) = ov;
        }
    }
}

// ---------------------------------------------------------------------------
// Split-KV flash attention. Grid (32 q-tiles, 8 heads, 4 kv-parts) = 1024
// equal blocks. No-max softmax is linear over kv, so partials (O_unnorm,
// rowsum) just add in the combine kernel. QK f16-accum, PV f32-accum,
// fp32 bias + softmax. Q fragments hoisted.
// ---------------------------------------------------------------------------
__global__ void __launch_bounds__(256, 2) attn_kernel(const float* __restrict__ bias) {
    extern __shared__ __half sm[];
    __half* Qs = sm;                         // [128][LDQ]
    __half* Ks = Qs + 128 * LDQ;             // [2][64][LDQ]
    __half* Vs = Ks + 2 * 64 * LDQ;          // [2][64][LDQ]

    const int h    = blockIdx.y;
    const int q0   = blockIdx.x * 128;
    const int part = blockIdx.z;
    const int kvb  = part * (NSEQ / KVPARTS);   // kv base for this part

    const int tid = threadIdx.x;
    const int warp = tid >> 5;
    const int lane = tid & 31;
    const int g  = lane >> 2;
    const int t  = lane & 3;

    for (int u = tid; u < 1024; u += 256) {
        const int row = u >> 3;
        const int c8  = (u & 7) * 8;
        *(uint4*)(Qs + row * LDQ + c8) =
            *(const uint4*)(g_qh + (size_t)(q0 + row) * HD + h * DDIM + c8);
    }

    float o[8][4];
#pragma unroll
    for (int j = 0; j < 8; j++)
#pragma unroll
        for (int e = 0; e < 4; e++) o[j][e] = 0.0f;
    float lrun[2] = {0.0f, 0.0f};

    const int a_row = 16 * warp + (lane & 15);
    const int a_ch  = (lane >> 4) * 8;
    const int b_row = ((lane >> 4) & 1) * 8 + (lane & 7);
    const int b_ch  = ((lane >> 3) & 1) * 8;
    const int v_row = ((lane >> 3) & 1) * 8 + (lane & 7);
    const int v_ch  = ((lane >> 4) & 1) * 8;

    const int cp_row = tid >> 2;
    const int cp_c8  = (tid & 3) * 16;

    // Prologue: K/V tile 0 of this part
    {
        const __half* kp = g_kh + (size_t)(kvb + cp_row) * HD + h * DDIM + cp_c8;
        const __half* vp = g_vh + (size_t)(kvb + cp_row) * HD + h * DDIM + cp_c8;
        uint32_t kd = smaddr(Ks + cp_row * LDQ + cp_c8);
        uint32_t vd = smaddr(Vs + cp_row * LDQ + cp_c8);
        cp_async16(kd, kp);           cp_async16(kd + 16, kp + 8);
        cp_async16(vd, vp);           cp_async16(vd + 16, vp + 8);
        cp_commit();
    }

    // Hoist Q fragments (Qs stable once loaded)
    __syncthreads();
    uint32_t qa[4][4];
#pragma unroll
    for (int kk = 0; kk < 4; kk++)
        ldsm_x4(qa[kk][0], qa[kk][1], qa[kk][2], qa[kk][3],
                smaddr(Qs + a_row * LDQ + 16 * kk + a_ch));

    const float* bias_base = bias + (size_t)(q0 + 16 * warp + g) * NSEQ;

    for (int kt = 0; kt < NTP; kt++) {
        const int buf = kt & 1;
        __half* Kb = Ks + buf * 64 * LDQ;
        __half* Vb = Vs + buf * 64 * LDQ;

        __syncthreads();

        // Prefetch tile kt+1
        if (kt + 1 < NTP) {
            const int k0n = kvb + (kt + 1) * 64;
            const __half* kp = g_kh + (size_t)(k0n + cp_row) * HD + h * DDIM + cp_c8;
            const __half* vp = g_vh + (size_t)(k0n + cp_row) * HD + h * DDIM + cp_c8;
            uint32_t kd = smaddr(Ks + (buf ^ 1) * 64 * LDQ + cp_row * LDQ + cp_c8);
            uint32_t vd = smaddr(Vs + (buf ^ 1) * 64 * LDQ + cp_row * LDQ + cp_c8);
            cp_async16(kd, kp);       cp_async16(kd + 16, kp + 8);
            cp_async16(vd, vp);       cp_async16(vd + 16, vp + 8);
        }
        cp_commit();

        // Bias loads for tile kt (fp32; LDGs in flight during wait + mma)
        const int k0 = kvb + kt * 64;
        float2 bb0[8], bb1[8];
#pragma unroll
        for (int j = 0; j < 8; j++) {
            const int col = k0 + 8 * j + 2 * t;
            bb0[j] = *(const float2*)(bias_base + col);
            bb1[j] = *(const float2*)(bias_base + (size_t)8 * NSEQ + col);
        }

        cp_wait<1>();
        __syncthreads();

        // S = Q K^T  (f16 accumulate, zero-init)
        uint32_t sf[8][2];
#pragma unroll
        for (int j = 0; j < 8; j++) { sf[j][0] = 0u; sf[j][1] = 0u; }

#pragma unroll
        for (int kk = 0; kk < 4; kk++) {
#pragma unroll
            for (int jp = 0; jp < 4; jp++) {
                uint32_t b0, b1, b2, b3;
                ldsm_x4(b0, b1, b2, b3,
                        smaddr(Kb + (16 * jp + b_row) * LDQ + 16 * kk + b_ch));
                mma16816_h(sf[2 * jp],     qa[kk], b0, b1);
                mma16816_h(sf[2 * jp + 1], qa[kk], b2, b3);
            }
        }

        // Softmax without max-subtraction; pack P into A-fragments
        uint32_t pa[4][4];
#pragma unroll
        for (int j = 0; j < 8; j++) {
            float2 lo = __half22float2(*(const __half2*)&sf[j][0]);
            float2 hi = __half22float2(*(const __half2*)&sf[j][1]);
            const float p00 = __expf(lo.x + bb0[j].x);
            const float p01 = __expf(lo.y + bb0[j].y);
            const float p10 = __expf(hi.x + bb1[j].x);
            const float p11 = __expf(hi.y + bb1[j].y);
            lrun[0] += p00 + p01;
            lrun[1] += p10 + p11;
            const int m = j >> 1;
            const int hl = j & 1;
            pa[m][2 * hl]     = pack_f16x2(p00, p01);
            pa[m][2 * hl + 1] = pack_f16x2(p10, p11);
        }

        // O += P V (f32 accumulate)
#pragma unroll
        for (int m = 0; m < 4; m++) {
#pragma unroll
            for (int jp = 0; jp < 4; jp++) {
                uint32_t b0, b1, b2, b3;
                ldsm_x4_t(b0, b1, b2, b3,
                          smaddr(Vb + (16 * m + v_row) * LDQ + 16 * jp + v_ch));
                mma16816(o[2 * jp],     pa[m], b0, b1);
                mma16816(o[2 * jp + 1], pa[m], b2, b3);
            }
        }
    }

    // Reduce row sums across the 4 t-lanes
#pragma unroll
    for (int r = 0; r < 2; r++) {
        lrun[r] += __shfl_xor_sync(0xffffffffu, lrun[r], 1);
        lrun[r] += __shfl_xor_sync(0xffffffffu, lrun[r], 2);
    }

    // Epilogue: write unnormalized f32 partials + row sums for this part
    float* opart = g_opart[part];
#pragma unroll
    for (int r = 0; r < 2; r++) {
        const int row = q0 + 16 * warp + g + 8 * r;
        if (t == 0)
            g_ls[part][h * NSEQ + row] = lrun[r];
        const size_t rb = (size_t)row * HD + h * DDIM;
#pragma unroll
        for (int j = 0; j < 8; j++) {
            const int col = 8 * j + 2 * t;
            float2 ov;
            ov.x = o[j][2 * r];
            ov.y = o[j][2 * r + 1];
            *(float2*)(opart + rb + col) = ov;
        }
    }
}

// ---------------------------------------------------------------------------
// Combine: sum the 4 kv-part partials, normalize, gate, store fp16 g_oh.
// ---------------------------------------------------------------------------
__global__ void __launch_bounds__(256) combine_kernel() {
    const size_t idx = ((size_t)blockIdx.x * 256 + threadIdx.x) * 4;
    const int row = (int)(idx / HD);
    const int col = (int)(idx % HD);
    const int h   = col / DDIM;

    float4 s = *(const float4*)(g_opart[0] + idx);
    float4 s1 = *(const float4*)(g_opart[1] + idx);
    float4 s2 = *(const float4*)(g_opart[2] + idx);
    float4 s3 = *(const float4*)(g_opart[3] + idx);
    s.x += s1.x + s2.x + s3.x;
    s.y += s1.y + s2.y + s3.y;
    s.z += s1.z + s2.z + s3.z;
    s.w += s1.w + s2.w + s3.w;

    const int li = h * NSEQ + row;
    const float l = g_ls[0][li] + g_ls[1][li] + g_ls[2][li] + g_ls[3][li];
    const float inv = 1.0f / l;

    float4 gv = *(const float4*)(g_g + idx);
    uint2 p;
    p.x = pack_f16x2(s.x * inv * gv.x, s.y * inv * gv.y);
    p.y = pack_f16x2(s.z * inv * gv.z, s.w * inv * gv.w);
    *(uint2*)(g_oh + idx) = p;
}

// ---------------------------------------------------------------------------
extern "C" void kernel_launch(void* const* d_in, const int* in_sizes, int n_in,
                              void* d_out, int out_size) {
    const float* q_x  = (const float*)d_in[0];
    const float* k_x  = (const float*)d_in[1];
    const float* v_x  = (const float*)d_in[2];
    const float* bias = (const float*)d_in[3];
    const float* wq   = (const float*)d_in[4];
    const float* wk   = (const float*)d_in[5];
    const float* wv   = (const float*)d_in[6];
    const float* wg   = (const float*)d_in[7];
    const float* bg   = (const float*)d_in[8];
    const float* wo   = (const float*)d_in[9];
    const float* bo   = (const float*)d_in[10];
    float* out = (float*)d_out;

    proj_all<<<dim3(HD / 64, NSEQ / 128, 4), 256>>>(q_x, k_x, v_x, wq, wk, wv, wg, bg);

    const size_t smem = (size_t)(128 + 4 * 64) * LDQ * sizeof(__half);  // 55296 B
    cudaFuncSetAttribute(attn_kernel, cudaFuncAttributeMaxDynamicSharedMemorySize, (int)smem);
    attn_kernel<<<dim3(NSEQ / 128, HEADS, KVPARTS), 256, smem>>>(bias);

    combine_kernel<<<(NSEQ * HD) / 1024, 256>>>();

    out_gemm<<<dim3(CDIM / 64, NSEQ / 128), 256>>>(wo, bo, out);
}